// round 1
// baseline (speedup 1.0000x reference)
#include <cuda_runtime.h>
#include <math.h>

#define Bv 2
#define Tv 2048
#define Dv 1024
#define Hv 16
#define HDv 64
#define QKV_N 3072
#define Mv (Bv*Tv)   // 4096

// Scratch (device globals — no allocations allowed)
__device__ float g_Q[Bv*Hv*Tv*HDv];   // [B,H,T,hd]
__device__ float g_K[Bv*Hv*Tv*HDv];
__device__ float g_V[Bv*Hv*Tv*HDv];
__device__ float g_Att[Bv*Tv*Dv];     // [B,T,D] (attn out, pre out-proj)

// ---------------------------------------------------------------------------
// GEMM: C[M,N] = A[M,K] @ W[N,K]^T + bias
// MODE 0: A = x, scatter into g_Q/g_K/g_V with head remap (N=3072)
// MODE 1: A = g_Att, write C = d_out (N=1024)
// Tiles: 128x128x16, 256 threads, 8x8 per thread.
// ---------------------------------------------------------------------------
template<int MODE>
__global__ __launch_bounds__(256) void gemm_kernel(const float* __restrict__ Ain,
                                                   const float* __restrict__ W,
                                                   const float* __restrict__ bias,
                                                   float* __restrict__ C) {
    const int K = 1024;
    __shared__ float As[16][128];
    __shared__ float Bs[16][128];

    const float* A = (MODE == 0) ? Ain : g_Att;

    const int m0 = blockIdx.y * 128;
    const int n0 = blockIdx.x * 128;
    const int t  = threadIdx.x;
    const int ty = t >> 4, tx = t & 15;

    float acc[8][8];
    #pragma unroll
    for (int i = 0; i < 8; i++)
        #pragma unroll
        for (int j = 0; j < 8; j++) acc[i][j] = 0.0f;

    for (int k0 = 0; k0 < K; k0 += 16) {
        #pragma unroll
        for (int l = 0; l < 2; l++) {
            int idx = t + l * 256;          // 0..511
            int row = idx >> 2;             // 0..127
            int c4  = (idx & 3) * 4;        // 0,4,8,12
            float4 av = *reinterpret_cast<const float4*>(A + (size_t)(m0 + row) * K + k0 + c4);
            As[c4 + 0][row] = av.x; As[c4 + 1][row] = av.y;
            As[c4 + 2][row] = av.z; As[c4 + 3][row] = av.w;
            float4 wv = *reinterpret_cast<const float4*>(W + (size_t)(n0 + row) * K + k0 + c4);
            Bs[c4 + 0][row] = wv.x; Bs[c4 + 1][row] = wv.y;
            Bs[c4 + 2][row] = wv.z; Bs[c4 + 3][row] = wv.w;
        }
        __syncthreads();

        #pragma unroll
        for (int kk = 0; kk < 16; kk++) {
            float a[8], b[8];
            *reinterpret_cast<float4*>(a)     = *reinterpret_cast<const float4*>(&As[kk][ty * 8]);
            *reinterpret_cast<float4*>(a + 4) = *reinterpret_cast<const float4*>(&As[kk][ty * 8 + 4]);
            *reinterpret_cast<float4*>(b)     = *reinterpret_cast<const float4*>(&Bs[kk][tx * 8]);
            *reinterpret_cast<float4*>(b + 4) = *reinterpret_cast<const float4*>(&Bs[kk][tx * 8 + 4]);
            #pragma unroll
            for (int i = 0; i < 8; i++)
                #pragma unroll
                for (int j = 0; j < 8; j++)
                    acc[i][j] = fmaf(a[i], b[j], acc[i][j]);
        }
        __syncthreads();
    }

    if (MODE == 0) {
        // scatter into Q/K/V: e = h*192 + r; r<64 -> Q, r<128 -> K, else V
        #pragma unroll
        for (int i = 0; i < 8; i++) {
            int m  = m0 + ty * 8 + i;
            int bb = m >> 11;            // / T
            int tt = m & (Tv - 1);
            #pragma unroll
            for (int j = 0; j < 8; j++) {
                int e = n0 + tx * 8 + j;
                float v = acc[i][j] + bias[e];
                int h = e / 192;
                int r = e - h * 192;
                int rr = r & 63;
                size_t off = (((size_t)(bb * Hv + h)) * Tv + tt) * HDv + rr;
                if (r < 64)       g_Q[off] = v;
                else if (r < 128) g_K[off] = v;
                else              g_V[off] = v;
            }
        }
    } else {
        #pragma unroll
        for (int i = 0; i < 8; i++) {
            int m = m0 + ty * 8 + i;
            int n = n0 + tx * 8;
            float4 o0, o1;
            o0.x = acc[i][0] + bias[n + 0]; o0.y = acc[i][1] + bias[n + 1];
            o0.z = acc[i][2] + bias[n + 2]; o0.w = acc[i][3] + bias[n + 3];
            o1.x = acc[i][4] + bias[n + 4]; o1.y = acc[i][5] + bias[n + 5];
            o1.z = acc[i][6] + bias[n + 6]; o1.w = acc[i][7] + bias[n + 7];
            *reinterpret_cast<float4*>(C + (size_t)m * Dv + n)     = o0;
            *reinterpret_cast<float4*>(C + (size_t)m * Dv + n + 4) = o1;
        }
    }
}

// ---------------------------------------------------------------------------
// Flash attention, fp32, causal. One CTA per (b*H+h, 64-query tile).
// 256 threads (16x16): thread owns 4 queries x 4 value-dims.
// Shared: Qs/Ks transposed [d][q] stride 68, Vs [k][d] stride 68, Ps [q][k] stride 68.
// ---------------------------------------------------------------------------
#define PAD 68

__global__ __launch_bounds__(256) void flash_attn_kernel() {
    extern __shared__ float sm[];
    float* Qs = sm;                 // [64][PAD] layout [d][q]
    float* Ks = Qs + 64 * PAD;      // [d][k]
    float* Vs = Ks + 64 * PAD;      // [k][d]
    float* Ps = Vs + 64 * PAD;      // [q][k]

    const int bh = blockIdx.y;              // 0..31
    const int bb = bh >> 4;
    const int h  = bh & 15;
    const int qt = blockIdx.x;
    const int q0 = qt * 64;

    const float* Qg  = g_Q + ((size_t)bh * Tv + q0) * HDv;
    const float* Kg0 = g_K + (size_t)bh * Tv * HDv;
    const float* Vg0 = g_V + (size_t)bh * Tv * HDv;

    const int t  = threadIdx.x;
    const int ty = t >> 4, tx = t & 15;

    // Load Q tile transposed: Qs[d][qy]
    #pragma unroll
    for (int l = 0; l < 4; l++) {
        int idx = t + l * 256;          // 0..1023
        int qy  = idx >> 4;             // 0..63
        int d4  = (idx & 15) * 4;       // 0..60
        float4 v = *reinterpret_cast<const float4*>(Qg + qy * HDv + d4);
        Qs[(d4 + 0) * PAD + qy] = v.x; Qs[(d4 + 1) * PAD + qy] = v.y;
        Qs[(d4 + 2) * PAD + qy] = v.z; Qs[(d4 + 3) * PAD + qy] = v.w;
    }

    float m_i[4], l_i[4], acc[4][4];
    #pragma unroll
    for (int i = 0; i < 4; i++) {
        m_i[i] = -INFINITY; l_i[i] = 0.0f;
        #pragma unroll
        for (int j = 0; j < 4; j++) acc[i][j] = 0.0f;
    }

    for (int kt = 0; kt <= qt; kt++) {
        __syncthreads();   // previous iteration's Ps/Vs reads done
        const int k0 = kt * 64;

        // Load K (transposed) and V (natural) tiles
        #pragma unroll
        for (int l = 0; l < 4; l++) {
            int idx = t + l * 256;
            int ky  = idx >> 4;
            int d4  = (idx & 15) * 4;
            float4 kv = *reinterpret_cast<const float4*>(Kg0 + (size_t)(k0 + ky) * HDv + d4);
            Ks[(d4 + 0) * PAD + ky] = kv.x; Ks[(d4 + 1) * PAD + ky] = kv.y;
            Ks[(d4 + 2) * PAD + ky] = kv.z; Ks[(d4 + 3) * PAD + ky] = kv.w;
            float4 vv = *reinterpret_cast<const float4*>(Vg0 + (size_t)(k0 + ky) * HDv + d4);
            *reinterpret_cast<float4*>(Vs + ky * PAD + d4) = vv;
        }
        __syncthreads();

        // S = Q @ K^T (thread: 4 queries ty*4+i  x  4 keys tx*4+j)
        float s[4][4];
        #pragma unroll
        for (int i = 0; i < 4; i++)
            #pragma unroll
            for (int j = 0; j < 4; j++) s[i][j] = 0.0f;

        #pragma unroll
        for (int d = 0; d < 64; d++) {
            float4 qv = *reinterpret_cast<const float4*>(Qs + d * PAD + ty * 4);
            float4 kv = *reinterpret_cast<const float4*>(Ks + d * PAD + tx * 4);
            float qa[4] = {qv.x, qv.y, qv.z, qv.w};
            float ka[4] = {kv.x, kv.y, kv.z, kv.w};
            #pragma unroll
            for (int i = 0; i < 4; i++)
                #pragma unroll
                for (int j = 0; j < 4; j++)
                    s[i][j] = fmaf(qa[i], ka[j], s[i][j]);
        }

        const bool diag = (kt == qt);
        #pragma unroll
        for (int i = 0; i < 4; i++)
            #pragma unroll
            for (int j = 0; j < 4; j++) {
                float sv = s[i][j] * 0.125f;   // 1/sqrt(64)
                if (diag && (k0 + tx * 4 + j > q0 + ty * 4 + i)) sv = -INFINITY;
                s[i][j] = sv;
            }

        // Online softmax (row groups = 16 lanes sharing ty)
        #pragma unroll
        for (int i = 0; i < 4; i++) {
            float mx = fmaxf(fmaxf(s[i][0], s[i][1]), fmaxf(s[i][2], s[i][3]));
            #pragma unroll
            for (int off = 8; off >= 1; off >>= 1)
                mx = fmaxf(mx, __shfl_xor_sync(0xffffffffu, mx, off));
            float mnew = fmaxf(m_i[i], mx);
            float corr = __expf(m_i[i] - mnew);
            m_i[i] = mnew;
            float rs = 0.0f;
            #pragma unroll
            for (int j = 0; j < 4; j++) {
                float p = __expf(s[i][j] - mnew);
                s[i][j] = p;
                rs += p;
            }
            #pragma unroll
            for (int off = 8; off >= 1; off >>= 1)
                rs += __shfl_xor_sync(0xffffffffu, rs, off);
            l_i[i] = l_i[i] * corr + rs;
            #pragma unroll
            for (int j = 0; j < 4; j++) acc[i][j] *= corr;
        }

        // Store P to shared: Ps[q][k]
        #pragma unroll
        for (int i = 0; i < 4; i++) {
            float4 pv = make_float4(s[i][0], s[i][1], s[i][2], s[i][3]);
            *reinterpret_cast<float4*>(Ps + (ty * 4 + i) * PAD + tx * 4) = pv;
        }
        __syncthreads();

        // O += P @ V  (thread: 4 queries x 4 value-dims tx*4+j)
        #pragma unroll
        for (int ky = 0; ky < 64; ky++) {
            float4 vv = *reinterpret_cast<const float4*>(Vs + ky * PAD + tx * 4);
            float va[4] = {vv.x, vv.y, vv.z, vv.w};
            #pragma unroll
            for (int i = 0; i < 4; i++) {
                float p = Ps[(ty * 4 + i) * PAD + ky];
                #pragma unroll
                for (int j = 0; j < 4; j++)
                    acc[i][j] = fmaf(p, va[j], acc[i][j]);
            }
        }
    }

    // Finalize: divide by l, write to g_Att in [B,T,D] layout
    #pragma unroll
    for (int i = 0; i < 4; i++) {
        float inv = 1.0f / l_i[i];
        int tq = q0 + ty * 4 + i;
        float4 o = make_float4(acc[i][0] * inv, acc[i][1] * inv,
                               acc[i][2] * inv, acc[i][3] * inv);
        *reinterpret_cast<float4*>(g_Att + ((size_t)bb * Tv + tq) * Dv + h * HDv + tx * 4) = o;
    }
}

// ---------------------------------------------------------------------------
extern "C" void kernel_launch(void* const* d_in, const int* in_sizes, int n_in,
                              void* d_out, int out_size) {
    const float* x     = (const float*)d_in[0];
    const float* Wqkv  = (const float*)d_in[1];
    const float* bqkv  = (const float*)d_in[2];
    const float* Wout  = (const float*)d_in[3];
    const float* bout  = (const float*)d_in[4];
    float* out = (float*)d_out;

    // 1) QKV projection + head-layout scatter
    gemm_kernel<0><<<dim3(QKV_N / 128, Mv / 128), 256>>>(x, Wqkv, bqkv, nullptr);

    // 2) Causal flash attention
    size_t smem = (size_t)4 * 64 * PAD * sizeof(float);   // 69,632 B
    cudaFuncSetAttribute(flash_attn_kernel,
                         cudaFuncAttributeMaxDynamicSharedMemorySize, (int)smem);
    flash_attn_kernel<<<dim3(Tv / 64, Bv * Hv), 256, smem>>>();

    // 3) Output projection
    gemm_kernel<1><<<dim3(Dv / 128, Mv / 128), 256>>>(nullptr, Wout, bout, out);
}

// round 5
// speedup vs baseline: 1.4044x; 1.4044x over previous
#include <cuda_runtime.h>
#include <cuda_bf16.h>
#include <math.h>
#include <stdint.h>

#define Bv 2
#define Tv 2048
#define Dv 1024
#define Hv 16
#define HDv 64
#define Mv 4096          // B*T
#define Kv 1024
#define QKV_N 3072

// ---------------- device scratch (no allocations allowed) ------------------
__device__ __align__(16) float g_Q[Bv*Hv*Tv*HDv];
__device__ __align__(16) float g_K[Bv*Hv*Tv*HDv];
__device__ __align__(16) float g_V[Bv*Hv*Tv*HDv];
__device__ __align__(16) float g_Att[Mv*Dv];

__device__ __align__(16) __nv_bfloat16 g_xh[Mv*Kv],     g_xl[Mv*Kv];
__device__ __align__(16) __nv_bfloat16 g_wqh[QKV_N*Kv], g_wql[QKV_N*Kv];
__device__ __align__(16) __nv_bfloat16 g_ah[Mv*Kv],     g_al[Mv*Kv];
__device__ __align__(16) __nv_bfloat16 g_woh[Dv*Kv],    g_wol[Dv*Kv];

// ---------------- PTX helpers (family-generic: HMMA/ldmatrix/cp.async) -----
__device__ __forceinline__ uint32_t smem_u32(const void* p) {
    uint32_t a;
    asm("{ .reg .u64 t; cvta.to.shared.u64 t, %1; cvt.u32.u64 %0, t; }" : "=r"(a) : "l"(p));
    return a;
}
__device__ __forceinline__ void cp16(uint32_t s, const void* g) {
    asm volatile("cp.async.cg.shared.global [%0], [%1], 16;" :: "r"(s), "l"(g));
}
#define CP_COMMIT()  asm volatile("cp.async.commit_group;" ::: "memory")
#define CP_WAIT_1()  asm volatile("cp.async.wait_group 1;" ::: "memory")
#define CP_WAIT_0()  asm volatile("cp.async.wait_group 0;" ::: "memory")

__device__ __forceinline__ void ldm_x4(uint32_t* r, uint32_t a) {
    asm volatile("ldmatrix.sync.aligned.m8n8.x4.shared.b16 {%0,%1,%2,%3}, [%4];"
        : "=r"(r[0]), "=r"(r[1]), "=r"(r[2]), "=r"(r[3]) : "r"(a));
}
__device__ __forceinline__ void mma_bf16(float* d, const uint32_t* a,
                                         uint32_t b0, uint32_t b1) {
    asm volatile(
        "mma.sync.aligned.m16n8k16.row.col.f32.bf16.bf16.f32 "
        "{%0,%1,%2,%3}, {%4,%5,%6,%7}, {%8,%9}, {%0,%1,%2,%3};"
        : "+f"(d[0]), "+f"(d[1]), "+f"(d[2]), "+f"(d[3])
        : "r"(a[0]), "r"(a[1]), "r"(a[2]), "r"(a[3]), "r"(b0), "r"(b1));
}

// ---------------- split fp32 -> (hi, lo) bf16 -------------------------------
__global__ __launch_bounds__(256) void split_kernel(const float* __restrict__ s,
                                                    __nv_bfloat16* __restrict__ hi,
                                                    __nv_bfloat16* __restrict__ lo,
                                                    int n4) {
    int i = blockIdx.x * blockDim.x + threadIdx.x;
    if (i >= n4) return;
    float4 v = reinterpret_cast<const float4*>(s)[i];
    ushort4 h, l;
    __nv_bfloat16 b;
    b = __float2bfloat16(v.x); h.x = __bfloat16_as_ushort(b);
    l.x = __bfloat16_as_ushort(__float2bfloat16(v.x - __bfloat162float(b)));
    b = __float2bfloat16(v.y); h.y = __bfloat16_as_ushort(b);
    l.y = __bfloat16_as_ushort(__float2bfloat16(v.y - __bfloat162float(b)));
    b = __float2bfloat16(v.z); h.z = __bfloat16_as_ushort(b);
    l.z = __bfloat16_as_ushort(__float2bfloat16(v.z - __bfloat162float(b)));
    b = __float2bfloat16(v.w); h.w = __bfloat16_as_ushort(b);
    l.w = __bfloat16_as_ushort(__float2bfloat16(v.w - __bfloat162float(b)));
    reinterpret_cast<ushort4*>(hi)[i] = h;
    reinterpret_cast<ushort4*>(lo)[i] = l;
}

// ---------------- HMMA GEMM: C[M,N] = A[M,K] @ W[N,K]^T + bias --------------
// Split precision: acc += Ah*Bh + Ah*Bl + Al*Bh in fp32 (mma.sync bf16).
// 128x128 CTA tile, BK=32, 8 warps (2x4), warp tile 64x32.
// SMEM row stride 40 bf16 (80B): banks r*20 mod 32 distinct -> ldmatrix clean.
// MODE 0: scatter into g_Q/g_K/g_V; MODE 1: write C + bias.

#define RS     40                 // SMEM row stride in bf16 elements
#define TILE_B (128 * RS * 2)     // 10240 B per 128x32 bf16 tile
#define STG_B  (4 * TILE_B)       // Ah, Al, Bh, Bl per stage = 40960 B

__global__ __launch_bounds__(256, 1) void gemm_mma(const __nv_bfloat16* __restrict__ Ah,
                                                   const __nv_bfloat16* __restrict__ Al,
                                                   const __nv_bfloat16* __restrict__ Bh,
                                                   const __nv_bfloat16* __restrict__ Bl,
                                                   const float* __restrict__ bias,
                                                   float* __restrict__ C, int MODE) {
    extern __shared__ __align__(1024) char dsm[];
    const uint32_t dsb = smem_u32(dsm);

    const int t    = threadIdx.x;
    const int lane = t & 31;
    const int wid  = t >> 5;
    const int wm   = wid & 1;        // 0..1 -> 64 rows
    const int wn   = wid >> 1;       // 0..3 -> 32 cols
    const int m0   = blockIdx.y * 128;
    const int n0   = blockIdx.x * 128;

    // cp.async geometry: 2 granules of 16B (8 bf16) per 128x32 tile per thread
    int      goff[2];
    uint32_t soff[2];
    #pragma unroll
    for (int i = 0; i < 2; i++) {
        int g   = t + i * 256;        // 0..511
        int row = g >> 2;
        int c8  = (g & 3) * 8;
        goff[i] = row * Kv + c8;
        soff[i] = (uint32_t)(row * RS + c8) * 2;
    }
    const __nv_bfloat16* Ahb = Ah + (size_t)m0 * Kv;
    const __nv_bfloat16* Alb = Al + (size_t)m0 * Kv;
    const __nv_bfloat16* Bhb = Bh + (size_t)n0 * Kv;
    const __nv_bfloat16* Blb =Bl + (size_t)n0 * Kv;

    // ldmatrix per-lane address bases (row = lane&15, k-half = lane>>4)
    const uint32_t a_base = dsb + (uint32_t)((wm * 64 + (lane & 15)) * RS + (lane >> 4) * 8) * 2;
    const uint32_t b_base = dsb + 2u * TILE_B
                          + (uint32_t)((wn * 32 + (lane & 15)) * RS + (lane >> 4) * 8) * 2;

    float acc[4][4][4];
    #pragma unroll
    for (int i = 0; i < 4; i++)
        #pragma unroll
        for (int n = 0; n < 4; n++)
            #pragma unroll
            for (int r = 0; r < 4; r++) acc[i][n][r] = 0.0f;

    // ---- issue chunk 0 ----
    #pragma unroll
    for (int i = 0; i < 2; i++) {
        cp16(dsb + soff[i],              Ahb + goff[i]);
        cp16(dsb + TILE_B + soff[i],     Alb + goff[i]);
        cp16(dsb + 2u*TILE_B + soff[i],  Bhb + goff[i]);
        cp16(dsb + 3u*TILE_B + soff[i],  Blb + goff[i]);
    }
    CP_COMMIT();

    const int NCHUNK = Kv / 32;   // 32
    for (int kt = 0; kt < NCHUNK; kt++) {
        const uint32_t s = (uint32_t)(kt & 1) * STG_B;
        if (kt + 1 < NCHUNK) {
            const uint32_t s1 = (uint32_t)((kt + 1) & 1) * STG_B;
            const int k1 = (kt + 1) * 32;
            #pragma unroll
            for (int i = 0; i < 2; i++) {
                cp16(dsb + s1 + soff[i],              Ahb + goff[i] + k1);
                cp16(dsb + s1 + TILE_B + soff[i],     Alb + goff[i] + k1);
                cp16(dsb + s1 + 2u*TILE_B + soff[i],  Bhb + goff[i] + k1);
                cp16(dsb + s1 + 3u*TILE_B + soff[i],  Blb + goff[i] + k1);
            }
            CP_COMMIT();
            CP_WAIT_1();
        } else {
            CP_WAIT_0();
        }
        __syncthreads();

        #pragma unroll
        for (int ks = 0; ks < 2; ks++) {           // two k16 steps in BK=32
            const uint32_t ko = (uint32_t)(ks * 16) * 2;
            uint32_t ah[4][4], al[4][4];
            #pragma unroll
            for (int i = 0; i < 4; i++) {
                ldm_x4(ah[i], a_base + s + ko + (uint32_t)i * (16 * RS * 2));
                ldm_x4(al[i], a_base + s + ko + TILE_B + (uint32_t)i * (16 * RS * 2));
            }
            uint32_t bh[2][4], bl[2][4];
            #pragma unroll
            for (int j = 0; j < 2; j++) {
                ldm_x4(bh[j], b_base + s + ko + (uint32_t)j * (16 * RS * 2));
                ldm_x4(bl[j], b_base + s + ko + TILE_B + (uint32_t)j * (16 * RS * 2));
            }
            #pragma unroll
            for (int i = 0; i < 4; i++)
                #pragma unroll
                for (int n = 0; n < 4; n++) {
                    const int jp = n >> 1, jo = n & 1;
                    mma_bf16(acc[i][n], ah[i], bh[jp][jo],     bh[jp][2 + jo]); // hi*hi
                    mma_bf16(acc[i][n], ah[i], bl[jp][jo],     bl[jp][2 + jo]); // hi*lo
                    mma_bf16(acc[i][n], al[i], bh[jp][jo],     bh[jp][2 + jo]); // lo*hi
                }
        }
        __syncthreads();
    }

    // ---- epilogue: bias + store ----
    if (MODE == 0) {
        #pragma unroll
        for (int i = 0; i < 4; i++)
            #pragma unroll
            for (int n = 0; n < 4; n++)
                #pragma unroll
                for (int r = 0; r < 4; r++) {
                    int row = m0 + wm * 64 + i * 16 + (lane >> 2) + (r >> 1) * 8;
                    int col = n0 + wn * 32 + n * 8 + (lane & 3) * 2 + (r & 1);
                    float v = acc[i][n][r] + __ldg(bias + col);
                    int bb = row >> 11;
                    int tt = row & (Tv - 1);
                    int h  = col / 192;
                    int rr = col - h * 192;
                    size_t off = (((size_t)(bb * Hv + h)) * Tv + tt) * HDv + (rr & 63);
                    if (rr < 64)       g_Q[off] = v;
                    else if (rr < 128) g_K[off] = v;
                    else               g_V[off] = v;
                }
    } else {
        #pragma unroll
        for (int i = 0; i < 4; i++)
            #pragma unroll
            for (int n = 0; n < 4; n++) {
                int row = m0 + wm * 64 + i * 16 + (lane >> 2);
                int col = n0 + wn * 32 + n * 8 + (lane & 3) * 2;
                float b0 = __ldg(bias + col), b1 = __ldg(bias + col + 1);
                float2 v0 = make_float2(acc[i][n][0] + b0, acc[i][n][1] + b1);
                float2 v1 = make_float2(acc[i][n][2] + b0, acc[i][n][3] + b1);
                *reinterpret_cast<float2*>(C + (size_t)row * Dv + col)       = v0;
                *reinterpret_cast<float2*>(C + (size_t)(row + 8) * Dv + col) = v1;
            }
    }
}

// ---------------- flash attention (fp32, unchanged) -------------------------
#define PAD 68
__global__ __launch_bounds__(256) void flash_attn_kernel() {
    extern __shared__ float sm[];
    float* Qs = sm;
    float* Ks = Qs + 64 * PAD;
    float* Vs = Ks + 64 * PAD;
    float* Ps = Vs + 64 * PAD;

    const int bh = blockIdx.y;
    const int bb = bh >> 4;
    const int h  = bh & 15;
    const int qt = blockIdx.x;
    const int q0 = qt * 64;

    const float* Qg  = g_Q + ((size_t)bh * Tv + q0) * HDv;
    const float* Kg0 = g_K + (size_t)bh * Tv * HDv;
    const float* Vg0 = g_V + (size_t)bh * Tv * HDv;

    const int t  = threadIdx.x;
    const int ty = t >> 4, tx = t & 15;

    #pragma unroll
    for (int l = 0; l < 4; l++) {
        int idx = t + l * 256;
        int qy  = idx >> 4;
        int d4  = (idx & 15) * 4;
        float4 v = *reinterpret_cast<const float4*>(Qg + qy * HDv + d4);
        Qs[(d4 + 0) * PAD + qy] = v.x; Qs[(d4 + 1) * PAD + qy] = v.y;
        Qs[(d4 + 2) * PAD + qy] = v.z; Qs[(d4 + 3) * PAD + qy] = v.w;
    }

    float m_i[4], l_i[4], acc[4][4];
    #pragma unroll
    for (int i = 0; i < 4; i++) {
        m_i[i] = -INFINITY; l_i[i] = 0.0f;
        #pragma unroll
        for (int j = 0; j < 4; j++) acc[i][j] = 0.0f;
    }

    for (int kt = 0; kt <= qt; kt++) {
        __syncthreads();
        const int k0 = kt * 64;
        #pragma unroll
        for (int l = 0; l < 4; l++) {
            int idx = t + l * 256;
            int ky  = idx >> 4;
            int d4  = (idx & 15) * 4;
            float4 kv = *reinterpret_cast<const float4*>(Kg0 + (size_t)(k0 + ky) * HDv + d4);
            Ks[(d4 + 0) * PAD + ky] = kv.x; Ks[(d4 + 1) * PAD + ky] = kv.y;
            Ks[(d4 + 2) * PAD + ky] = kv.z; Ks[(d4 + 3) * PAD + ky] = kv.w;
            float4 vv = *reinterpret_cast<const float4*>(Vg0 + (size_t)(k0 + ky) * HDv + d4);
            *reinterpret_cast<float4*>(Vs + ky * PAD + d4) = vv;
        }
        __syncthreads();

        float s[4][4];
        #pragma unroll
        for (int i = 0; i < 4; i++)
            #pragma unroll
            for (int j = 0; j < 4; j++) s[i][j] = 0.0f;
        #pragma unroll
        for (int d = 0; d < 64; d++) {
            float4 qv = *reinterpret_cast<const float4*>(Qs + d * PAD + ty * 4);
            float4 kv = *reinterpret_cast<const float4*>(Ks + d * PAD + tx * 4);
            float qa[4] = {qv.x, qv.y, qv.z, qv.w};
            float ka[4] = {kv.x, kv.y, kv.z, kv.w};
            #pragma unroll
            for (int i = 0; i < 4; i++)
                #pragma unroll
                for (int j = 0; j < 4; j++)
                    s[i][j] = fmaf(qa[i], ka[j], s[i][j]);
        }

        const bool diag = (kt == qt);
        #pragma unroll
        for (int i = 0; i < 4; i++)
            #pragma unroll
            for (int j = 0; j < 4; j++) {
                float sv = s[i][j] * 0.125f;
                if (diag && (k0 + tx * 4 + j > q0 + ty * 4 + i)) sv = -INFINITY;
                s[i][j] = sv;
            }

        #pragma unroll
        for (int i = 0; i < 4; i++) {
            float mx = fmaxf(fmaxf(s[i][0], s[i][1]), fmaxf(s[i][2], s[i][3]));
            #pragma unroll
            for (int off = 8; off >= 1; off >>= 1)
                mx = fmaxf(mx, __shfl_xor_sync(0xffffffffu, mx, off));
            float mnew = fmaxf(m_i[i], mx);
            float corr = __expf(m_i[i] - mnew);
            m_i[i] = mnew;
            float rs = 0.0f;
            #pragma unroll
            for (int j = 0; j < 4; j++) {
                float p = __expf(s[i][j] - mnew);
                s[i][j] = p;
                rs += p;
            }
            #pragma unroll
            for (int off = 8; off >= 1; off >>= 1)
                rs += __shfl_xor_sync(0xffffffffu, rs, off);
            l_i[i] = l_i[i] * corr + rs;
            #pragma unroll
            for (int j = 0; j < 4; j++) acc[i][j] *= corr;
        }

        #pragma unroll
        for (int i = 0; i < 4; i++) {
            float4 pv = make_float4(s[i][0], s[i][1], s[i][2], s[i][3]);
            *reinterpret_cast<float4*>(Ps + (ty * 4 + i) * PAD + tx * 4) = pv;
        }
        __syncthreads();

        #pragma unroll
        for (int ky = 0; ky < 64; ky++) {
            float4 vv = *reinterpret_cast<const float4*>(Vs + ky * PAD + tx * 4);
            float va[4] = {vv.x, vv.y, vv.z, vv.w};
            #pragma unroll
            for (int i = 0; i < 4; i++) {
                float p = Ps[(ty * 4 + i) * PAD + ky];
                #pragma unroll
                for (int j = 0; j < 4; j++)
                    acc[i][j] = fmaf(p, va[j], acc[i][j]);
            }
        }
    }

    #pragma unroll
    for (int i = 0; i < 4; i++) {
        float inv = 1.0f / l_i[i];
        int tq = q0 + ty * 4 + i;
        float4 o = make_float4(acc[i][0] * inv, acc[i][1] * inv,
                               acc[i][2] * inv, acc[i][3] * inv);
        *reinterpret_cast<float4*>(g_Att + ((size_t)bb * Tv + tq) * Dv + h * HDv + tx * 4) = o;
    }
}

// ---------------------------------------------------------------------------
extern "C" void kernel_launch(void* const* d_in, const int* in_sizes, int n_in,
                              void* d_out, int out_size) {
    const float* x    = (const float*)d_in[0];
    const float* Wqkv = (const float*)d_in[1];
    const float* bqkv = (const float*)d_in[2];
    const float* Wout = (const float*)d_in[3];
    const float* bout = (const float*)d_in[4];
    float* out = (float*)d_out;

    void *xh, *xl, *wqh, *wql, *ah, *al, *woh, *wol, *attp;
    cudaGetSymbolAddress(&xh,  g_xh);  cudaGetSymbolAddress(&xl,  g_xl);
    cudaGetSymbolAddress(&wqh, g_wqh); cudaGetSymbolAddress(&wql, g_wql);
    cudaGetSymbolAddress(&ah,  g_ah);  cudaGetSymbolAddress(&al,  g_al);
    cudaGetSymbolAddress(&woh, g_woh); cudaGetSymbolAddress(&wol, g_wol);
    cudaGetSymbolAddress(&attp, g_Att);

    cudaFuncSetAttribute(gemm_mma, cudaFuncAttributeMaxDynamicSharedMemorySize, 2 * STG_B);

    // fp32 -> (hi,lo) bf16 splits
    split_kernel<<<Mv * Kv / 1024, 256>>>(x, (__nv_bfloat16*)xh, (__nv_bfloat16*)xl, Mv * Kv / 4);
    split_kernel<<<QKV_N * Kv / 1024, 256>>>(Wqkv, (__nv_bfloat16*)wqh, (__nv_bfloat16*)wql, QKV_N * Kv / 4);
    split_kernel<<<Dv * Kv / 1024, 256>>>(Wout, (__nv_bfloat16*)woh, (__nv_bfloat16*)wol, Dv * Kv / 4);

    // 1) QKV projection (HMMA tensor cores) + head-layout scatter
    gemm_mma<<<dim3(QKV_N / 128, Mv / 128), 256, 2 * STG_B>>>(
        (__nv_bfloat16*)xh, (__nv_bfloat16*)xl, (__nv_bfloat16*)wqh, (__nv_bfloat16*)wql,
        bqkv, nullptr, 0);

    // 2) causal flash attention (fp32)
    size_t smem = (size_t)4 * 64 * PAD * sizeof(float);
    cudaFuncSetAttribute(flash_attn_kernel, cudaFuncAttributeMaxDynamicSharedMemorySize, (int)smem);
    flash_attn_kernel<<<dim3(Tv / 64, Bv * Hv), 256, smem>>>();

    // 3) split attention output, then output projection (HMMA)
    split_kernel<<<Mv * Dv / 1024, 256>>>((const float*)attp, (__nv_bfloat16*)ah, (__nv_bfloat16*)al, Mv * Dv / 4);
    gemm_mma<<<dim3(Dv / 128, Mv / 128), 256, 2 * STG_B>>>(
        (__nv_bfloat16*)ah, (__nv_bfloat16*)al, (__nv_bfloat16*)woh, (__nv_bfloat16*)wol,
        bout, out, 1);
}

// round 6
// speedup vs baseline: 1.4183x; 1.0099x over previous
#include <cuda_runtime.h>
#include <cuda_bf16.h>
#include <math.h>
#include <stdint.h>

#define Bv 2
#define Tv 2048
#define Dv 1024
#define Hv 16
#define HDv 64
#define Mv 4096          // B*T
#define Kv 1024
#define QKV_N 3072

// ---------------- device scratch (no allocations allowed) ------------------
__device__ __align__(16) float g_Q[Bv*Hv*Tv*HDv];
__device__ __align__(16) float g_K[Bv*Hv*Tv*HDv];
__device__ __align__(16) float g_V[Bv*Hv*Tv*HDv];
__device__ __align__(16) float g_Att[Mv*Dv];

__device__ __align__(16) __nv_bfloat16 g_xh[Mv*Kv],     g_xl[Mv*Kv];
__device__ __align__(16) __nv_bfloat16 g_wqh[QKV_N*Kv], g_wql[QKV_N*Kv];
__device__ __align__(16) __nv_bfloat16 g_ah[Mv*Kv],     g_al[Mv*Kv];
__device__ __align__(16) __nv_bfloat16 g_woh[Dv*Kv],    g_wol[Dv*Kv];

// ---------------- PTX helpers (family-generic: HMMA/ldmatrix/cp.async) -----
__device__ __forceinline__ uint32_t smem_u32(const void* p) {
    uint32_t a;
    asm("{ .reg .u64 t; cvta.to.shared.u64 t, %1; cvt.u32.u64 %0, t; }" : "=r"(a) : "l"(p));
    return a;
}
__device__ __forceinline__ void cp16(uint32_t s, const void* g) {
    asm volatile("cp.async.cg.shared.global [%0], [%1], 16;" :: "r"(s), "l"(g));
}
#define CP_COMMIT()  asm volatile("cp.async.commit_group;" ::: "memory")
#define CP_WAIT_1()  asm volatile("cp.async.wait_group 1;" ::: "memory")
#define CP_WAIT_0()  asm volatile("cp.async.wait_group 0;" ::: "memory")

__device__ __forceinline__ void ldm_x4(uint32_t* r, uint32_t a) {
    asm volatile("ldmatrix.sync.aligned.m8n8.x4.shared.b16 {%0,%1,%2,%3}, [%4];"
        : "=r"(r[0]), "=r"(r[1]), "=r"(r[2]), "=r"(r[3]) : "r"(a));
}
__device__ __forceinline__ void mma_bf16(float* d, const uint32_t* a,
                                         uint32_t b0, uint32_t b1) {
    asm volatile(
        "mma.sync.aligned.m16n8k16.row.col.f32.bf16.bf16.f32 "
        "{%0,%1,%2,%3}, {%4,%5,%6,%7}, {%8,%9}, {%0,%1,%2,%3};"
        : "+f"(d[0]), "+f"(d[1]), "+f"(d[2]), "+f"(d[3])
        : "r"(a[0]), "r"(a[1]), "r"(a[2]), "r"(a[3]), "r"(b0), "r"(b1));
}

// ---------------- split fp32 -> (hi, lo) bf16 -------------------------------
__global__ __launch_bounds__(256) void split_kernel(const float* __restrict__ s,
                                                    __nv_bfloat16* __restrict__ hi,
                                                    __nv_bfloat16* __restrict__ lo,
                                                    int n4) {
    int i = blockIdx.x * blockDim.x + threadIdx.x;
    if (i >= n4) return;
    float4 v = reinterpret_cast<const float4*>(s)[i];
    ushort4 h, l;
    __nv_bfloat16 b;
    b = __float2bfloat16(v.x); h.x = __bfloat16_as_ushort(b);
    l.x = __bfloat16_as_ushort(__float2bfloat16(v.x - __bfloat162float(b)));
    b = __float2bfloat16(v.y); h.y = __bfloat16_as_ushort(b);
    l.y = __bfloat16_as_ushort(__float2bfloat16(v.y - __bfloat162float(b)));
    b = __float2bfloat16(v.z); h.z = __bfloat16_as_ushort(b);
    l.z = __bfloat16_as_ushort(__float2bfloat16(v.z - __bfloat162float(b)));
    b = __float2bfloat16(v.w); h.w = __bfloat16_as_ushort(b);
    l.w = __bfloat16_as_ushort(__float2bfloat16(v.w - __bfloat162float(b)));
    reinterpret_cast<ushort4*>(hi)[i] = h;
    reinterpret_cast<ushort4*>(lo)[i] = l;
}

// ---------------- HMMA GEMM: C[M,N] = A[M,K] @ W[N,K]^T + bias --------------
// Split precision: acc += Ah*Bh + Ah*Bl + Al*Bh in fp32 (mma.sync bf16).
// 128x128 CTA tile, BK=32, 8 warps (2x4), warp tile 64x32.
// SMEM row stride 40 bf16 (80B): banks r*20 mod 32 distinct -> ldmatrix clean.
// MODE 0: scatter into g_Q/g_K/g_V; MODE 1: write C + bias.

#define RS     40                 // SMEM row stride in bf16 elements
#define TILE_B (128 * RS * 2)     // 10240 B per 128x32 bf16 tile
#define STG_B  (4 * TILE_B)       // Ah, Al, Bh, Bl per stage = 40960 B

__global__ __launch_bounds__(256, 1) void gemm_mma(const __nv_bfloat16* __restrict__ Ah,
                                                   const __nv_bfloat16* __restrict__ Al,
                                                   const __nv_bfloat16* __restrict__ Bh,
                                                   const __nv_bfloat16* __restrict__ Bl,
                                                   const float* __restrict__ bias,
                                                   float* __restrict__ C, int MODE) {
    extern __shared__ __align__(1024) char dsm[];
    const uint32_t dsb = smem_u32(dsm);

    const int t    = threadIdx.x;
    const int lane = t & 31;
    const int wid  = t >> 5;
    const int wm   = wid & 1;        // 0..1 -> 64 rows
    const int wn   = wid >> 1;       // 0..3 -> 32 cols
    const int m0   = blockIdx.y * 128;
    const int n0   = blockIdx.x * 128;

    // cp.async geometry: 2 granules of 16B (8 bf16) per 128x32 tile per thread
    int      goff[2];
    uint32_t soff[2];
    #pragma unroll
    for (int i = 0; i < 2; i++) {
        int g   = t + i * 256;        // 0..511
        int row = g >> 2;
        int c8  = (g & 3) * 8;
        goff[i] = row * Kv + c8;
        soff[i] = (uint32_t)(row * RS + c8) * 2;
    }
    const __nv_bfloat16* Ahb = Ah + (size_t)m0 * Kv;
    const __nv_bfloat16* Alb = Al + (size_t)m0 * Kv;
    const __nv_bfloat16* Bhb = Bh + (size_t)n0 * Kv;
    const __nv_bfloat16* Blb =Bl + (size_t)n0 * Kv;

    // ldmatrix per-lane address bases (row = lane&15, k-half = lane>>4)
    const uint32_t a_base = dsb + (uint32_t)((wm * 64 + (lane & 15)) * RS + (lane >> 4) * 8) * 2;
    const uint32_t b_base = dsb + 2u * TILE_B
                          + (uint32_t)((wn * 32 + (lane & 15)) * RS + (lane >> 4) * 8) * 2;

    float acc[4][4][4];
    #pragma unroll
    for (int i = 0; i < 4; i++)
        #pragma unroll
        for (int n = 0; n < 4; n++)
            #pragma unroll
            for (int r = 0; r < 4; r++) acc[i][n][r] = 0.0f;

    // ---- issue chunk 0 ----
    #pragma unroll
    for (int i = 0; i < 2; i++) {
        cp16(dsb + soff[i],              Ahb + goff[i]);
        cp16(dsb + TILE_B + soff[i],     Alb + goff[i]);
        cp16(dsb + 2u*TILE_B + soff[i],  Bhb + goff[i]);
        cp16(dsb + 3u*TILE_B + soff[i],  Blb + goff[i]);
    }
    CP_COMMIT();

    const int NCHUNK = Kv / 32;   // 32
    for (int kt = 0; kt < NCHUNK; kt++) {
        const uint32_t s = (uint32_t)(kt & 1) * STG_B;
        if (kt + 1 < NCHUNK) {
            const uint32_t s1 = (uint32_t)((kt + 1) & 1) * STG_B;
            const int k1 = (kt + 1) * 32;
            #pragma unroll
            for (int i = 0; i < 2; i++) {
                cp16(dsb + s1 + soff[i],              Ahb + goff[i] + k1);
                cp16(dsb + s1 + TILE_B + soff[i],     Alb + goff[i] + k1);
                cp16(dsb + s1 + 2u*TILE_B + soff[i],  Bhb + goff[i] + k1);
                cp16(dsb + s1 + 3u*TILE_B + soff[i],  Blb + goff[i] + k1);
            }
            CP_COMMIT();
            CP_WAIT_1();
        } else {
            CP_WAIT_0();
        }
        __syncthreads();

        #pragma unroll
        for (int ks = 0; ks < 2; ks++) {           // two k16 steps in BK=32
            const uint32_t ko = (uint32_t)(ks * 16) * 2;
            uint32_t ah[4][4], al[4][4];
            #pragma unroll
            for (int i = 0; i < 4; i++) {
                ldm_x4(ah[i], a_base + s + ko + (uint32_t)i * (16 * RS * 2));
                ldm_x4(al[i], a_base + s + ko + TILE_B + (uint32_t)i * (16 * RS * 2));
            }
            uint32_t bh[2][4], bl[2][4];
            #pragma unroll
            for (int j = 0; j < 2; j++) {
                ldm_x4(bh[j], b_base + s + ko + (uint32_t)j * (16 * RS * 2));
                ldm_x4(bl[j], b_base + s + ko + TILE_B + (uint32_t)j * (16 * RS * 2));
            }
            #pragma unroll
            for (int i = 0; i < 4; i++)
                #pragma unroll
                for (int n = 0; n < 4; n++) {
                    const int jp = n >> 1, jo = n & 1;
                    mma_bf16(acc[i][n], ah[i], bh[jp][jo],     bh[jp][2 + jo]); // hi*hi
                    mma_bf16(acc[i][n], ah[i], bl[jp][jo],     bl[jp][2 + jo]); // hi*lo
                    mma_bf16(acc[i][n], al[i], bh[jp][jo],     bh[jp][2 + jo]); // lo*hi
                }
        }
        __syncthreads();
    }

    // ---- epilogue: bias + store ----
    if (MODE == 0) {
        #pragma unroll
        for (int i = 0; i < 4; i++)
            #pragma unroll
            for (int n = 0; n < 4; n++)
                #pragma unroll
                for (int r = 0; r < 4; r++) {
                    int row = m0 + wm * 64 + i * 16 + (lane >> 2) + (r >> 1) * 8;
                    int col = n0 + wn * 32 + n * 8 + (lane & 3) * 2 + (r & 1);
                    float v = acc[i][n][r] + __ldg(bias + col);
                    int bb = row >> 11;
                    int tt = row & (Tv - 1);
                    int h  = col / 192;
                    int rr = col - h * 192;
                    size_t off = (((size_t)(bb * Hv + h)) * Tv + tt) * HDv + (rr & 63);
                    if (rr < 64)       g_Q[off] = v;
                    else if (rr < 128) g_K[off] = v;
                    else               g_V[off] = v;
                }
    } else {
        #pragma unroll
        for (int i = 0; i < 4; i++)
            #pragma unroll
            for (int n = 0; n < 4; n++) {
                int row = m0 + wm * 64 + i * 16 + (lane >> 2);
                int col = n0 + wn * 32 + n * 8 + (lane & 3) * 2;
                float b0 = __ldg(bias + col), b1 = __ldg(bias + col + 1);
                float2 v0 = make_float2(acc[i][n][0] + b0, acc[i][n][1] + b1);
                float2 v1 = make_float2(acc[i][n][2] + b0, acc[i][n][3] + b1);
                *reinterpret_cast<float2*>(C + (size_t)row * Dv + col)       = v0;
                *reinterpret_cast<float2*>(C + (size_t)(row + 8) * Dv + col) = v1;
            }
    }
}

// ---------------- flash attention (fp32, unchanged) -------------------------
#define PAD 68
__global__ __launch_bounds__(256) void flash_attn_kernel() {
    extern __shared__ float sm[];
    float* Qs = sm;
    float* Ks = Qs + 64 * PAD;
    float* Vs = Ks + 64 * PAD;
    float* Ps = Vs + 64 * PAD;

    const int bh = blockIdx.y;
    const int bb = bh >> 4;
    const int h  = bh & 15;
    const int qt = blockIdx.x;
    const int q0 = qt * 64;

    const float* Qg  = g_Q + ((size_t)bh * Tv + q0) * HDv;
    const float* Kg0 = g_K + (size_t)bh * Tv * HDv;
    const float* Vg0 = g_V + (size_t)bh * Tv * HDv;

    const int t  = threadIdx.x;
    const int ty = t >> 4, tx = t & 15;

    #pragma unroll
    for (int l = 0; l < 4; l++) {
        int idx = t + l * 256;
        int qy  = idx >> 4;
        int d4  = (idx & 15) * 4;
        float4 v = *reinterpret_cast<const float4*>(Qg + qy * HDv + d4);
        Qs[(d4 + 0) * PAD + qy] = v.x; Qs[(d4 + 1) * PAD + qy] = v.y;
        Qs[(d4 + 2) * PAD + qy] = v.z; Qs[(d4 + 3) * PAD + qy] = v.w;
    }

    float m_i[4], l_i[4], acc[4][4];
    #pragma unroll
    for (int i = 0; i < 4; i++) {
        m_i[i] = -INFINITY; l_i[i] = 0.0f;
        #pragma unroll
        for (int j = 0; j < 4; j++) acc[i][j] = 0.0f;
    }

    for (int kt = 0; kt <= qt; kt++) {
        __syncthreads();
        const int k0 = kt * 64;
        #pragma unroll
        for (int l = 0; l < 4; l++) {
            int idx = t + l * 256;
            int ky  = idx >> 4;
            int d4  = (idx & 15) * 4;
            float4 kv = *reinterpret_cast<const float4*>(Kg0 + (size_t)(k0 + ky) * HDv + d4);
            Ks[(d4 + 0) * PAD + ky] = kv.x; Ks[(d4 + 1) * PAD + ky] = kv.y;
            Ks[(d4 + 2) * PAD + ky] = kv.z; Ks[(d4 + 3) * PAD + ky] = kv.w;
            float4 vv = *reinterpret_cast<const float4*>(Vg0 + (size_t)(k0 + ky) * HDv + d4);
            *reinterpret_cast<float4*>(Vs + ky * PAD + d4) = vv;
        }
        __syncthreads();

        float s[4][4];
        #pragma unroll
        for (int i = 0; i < 4; i++)
            #pragma unroll
            for (int j = 0; j < 4; j++) s[i][j] = 0.0f;
        #pragma unroll
        for (int d = 0; d < 64; d++) {
            float4 qv = *reinterpret_cast<const float4*>(Qs + d * PAD + ty * 4);
            float4 kv = *reinterpret_cast<const float4*>(Ks + d * PAD + tx * 4);
            float qa[4] = {qv.x, qv.y, qv.z, qv.w};
            float ka[4] = {kv.x, kv.y, kv.z, kv.w};
            #pragma unroll
            for (int i = 0; i < 4; i++)
                #pragma unroll
                for (int j = 0; j < 4; j++)
                    s[i][j] = fmaf(qa[i], ka[j], s[i][j]);
        }

        const bool diag = (kt == qt);
        #pragma unroll
        for (int i = 0; i < 4; i++)
            #pragma unroll
            for (int j = 0; j < 4; j++) {
                float sv = s[i][j] * 0.125f;
                if (diag && (k0 + tx * 4 + j > q0 + ty * 4 + i)) sv = -INFINITY;
                s[i][j] = sv;
            }

        #pragma unroll
        for (int i = 0; i < 4; i++) {
            float mx = fmaxf(fmaxf(s[i][0], s[i][1]), fmaxf(s[i][2], s[i][3]));
            #pragma unroll
            for (int off = 8; off >= 1; off >>= 1)
                mx = fmaxf(mx, __shfl_xor_sync(0xffffffffu, mx, off));
            float mnew = fmaxf(m_i[i], mx);
            float corr = __expf(m_i[i] - mnew);
            m_i[i] = mnew;
            float rs = 0.0f;
            #pragma unroll
            for (int j = 0; j < 4; j++) {
                float p = __expf(s[i][j] - mnew);
                s[i][j] = p;
                rs += p;
            }
            #pragma unroll
            for (int off = 8; off >= 1; off >>= 1)
                rs += __shfl_xor_sync(0xffffffffu, rs, off);
            l_i[i] = l_i[i] * corr + rs;
            #pragma unroll
            for (int j = 0; j < 4; j++) acc[i][j] *= corr;
        }

        #pragma unroll
        for (int i = 0; i < 4; i++) {
            float4 pv = make_float4(s[i][0], s[i][1], s[i][2], s[i][3]);
            *reinterpret_cast<float4*>(Ps + (ty * 4 + i) * PAD + tx * 4) = pv;
        }
        __syncthreads();

        #pragma unroll
        for (int ky = 0; ky < 64; ky++) {
            float4 vv = *reinterpret_cast<const float4*>(Vs + ky * PAD + tx * 4);
            float va[4] = {vv.x, vv.y, vv.z, vv.w};
            #pragma unroll
            for (int i = 0; i < 4; i++) {
                float p = Ps[(ty * 4 + i) * PAD + ky];
                #pragma unroll
                for (int j = 0; j < 4; j++)
                    acc[i][j] = fmaf(p, va[j], acc[i][j]);
            }
        }
    }

    #pragma unroll
    for (int i = 0; i < 4; i++) {
        float inv = 1.0f / l_i[i];
        int tq = q0 + ty * 4 + i;
        float4 o = make_float4(acc[i][0] * inv, acc[i][1] * inv,
                               acc[i][2] * inv, acc[i][3] * inv);
        *reinterpret_cast<float4*>(g_Att + ((size_t)bb * Tv + tq) * Dv + h * HDv + tx * 4) = o;
    }
}

// ---------------------------------------------------------------------------
extern "C" void kernel_launch(void* const* d_in, const int* in_sizes, int n_in,
                              void* d_out, int out_size) {
    const float* x    = (const float*)d_in[0];
    const float* Wqkv = (const float*)d_in[1];
    const float* bqkv = (const float*)d_in[2];
    const float* Wout = (const float*)d_in[3];
    const float* bout = (const float*)d_in[4];
    float* out = (float*)d_out;

    void *xh, *xl, *wqh, *wql, *ah, *al, *woh, *wol, *attp;
    cudaGetSymbolAddress(&xh,  g_xh);  cudaGetSymbolAddress(&xl,  g_xl);
    cudaGetSymbolAddress(&wqh, g_wqh); cudaGetSymbolAddress(&wql, g_wql);
    cudaGetSymbolAddress(&ah,  g_ah);  cudaGetSymbolAddress(&al,  g_al);
    cudaGetSymbolAddress(&woh, g_woh); cudaGetSymbolAddress(&wol, g_wol);
    cudaGetSymbolAddress(&attp, g_Att);

    cudaFuncSetAttribute(gemm_mma, cudaFuncAttributeMaxDynamicSharedMemorySize, 2 * STG_B);

    // fp32 -> (hi,lo) bf16 splits
    split_kernel<<<Mv * Kv / 1024, 256>>>(x, (__nv_bfloat16*)xh, (__nv_bfloat16*)xl, Mv * Kv / 4);
    split_kernel<<<QKV_N * Kv / 1024, 256>>>(Wqkv, (__nv_bfloat16*)wqh, (__nv_bfloat16*)wql, QKV_N * Kv / 4);
    split_kernel<<<Dv * Kv / 1024, 256>>>(Wout, (__nv_bfloat16*)woh, (__nv_bfloat16*)wol, Dv * Kv / 4);

    // 1) QKV projection (HMMA tensor cores) + head-layout scatter
    gemm_mma<<<dim3(QKV_N / 128, Mv / 128), 256, 2 * STG_B>>>(
        (__nv_bfloat16*)xh, (__nv_bfloat16*)xl, (__nv_bfloat16*)wqh, (__nv_bfloat16*)wql,
        bqkv, nullptr, 0);

    // 2) causal flash attention (fp32)
    size_t smem = (size_t)4 * 64 * PAD * sizeof(float);
    cudaFuncSetAttribute(flash_attn_kernel, cudaFuncAttributeMaxDynamicSharedMemorySize, (int)smem);
    flash_attn_kernel<<<dim3(Tv / 64, Bv * Hv), 256, smem>>>();

    // 3) split attention output, then output projection (HMMA)
    split_kernel<<<Mv * Dv / 1024, 256>>>((const float*)attp, (__nv_bfloat16*)ah, (__nv_bfloat16*)al, Mv * Dv / 4);
    gemm_mma<<<dim3(Dv / 128, Mv / 128), 256, 2 * STG_B>>>(
        (__nv_bfloat16*)ah, (__nv_bfloat16*)al, (__nv_bfloat16*)woh, (__nv_bfloat16*)wol,
        bout, out, 1);
}

// round 7
// speedup vs baseline: 2.1719x; 1.5313x over previous
#include <cuda_runtime.h>
#include <cuda_bf16.h>
#include <math.h>
#include <stdint.h>

#define Bv 2
#define Tv 2048
#define Dv 1024
#define Hv 16
#define HDv 64
#define Mv 4096          // B*T
#define Kv 1024
#define QKV_N 3072

// ---------------- device scratch (no allocations allowed) ------------------
__device__ __align__(16) float g_Att[Mv*Dv];

__device__ __align__(16) __nv_bfloat16 g_Qh[Bv*Hv*Tv*HDv], g_Ql[Bv*Hv*Tv*HDv];
__device__ __align__(16) __nv_bfloat16 g_Kh[Bv*Hv*Tv*HDv], g_Kl[Bv*Hv*Tv*HDv];
__device__ __align__(16) __nv_bfloat16 g_Vh[Bv*Hv*Tv*HDv], g_Vl[Bv*Hv*Tv*HDv];

__device__ __align__(16) __nv_bfloat16 g_xh[Mv*Kv],     g_xl[Mv*Kv];
__device__ __align__(16) __nv_bfloat16 g_wqh[QKV_N*Kv], g_wql[QKV_N*Kv];
__device__ __align__(16) __nv_bfloat16 g_ah[Mv*Kv],     g_al[Mv*Kv];
__device__ __align__(16) __nv_bfloat16 g_woh[Dv*Kv],    g_wol[Dv*Kv];

// ---------------- PTX helpers ------------------------------------------------
__device__ __forceinline__ uint32_t smem_u32(const void* p) {
    uint32_t a;
    asm("{ .reg .u64 t; cvta.to.shared.u64 t, %1; cvt.u32.u64 %0, t; }" : "=r"(a) : "l"(p));
    return a;
}
__device__ __forceinline__ void cp16(uint32_t s, const void* g) {
    asm volatile("cp.async.cg.shared.global [%0], [%1], 16;" :: "r"(s), "l"(g));
}
#define CP_COMMIT()  asm volatile("cp.async.commit_group;" ::: "memory")
#define CP_WAIT_1()  asm volatile("cp.async.wait_group 1;" ::: "memory")
#define CP_WAIT_0()  asm volatile("cp.async.wait_group 0;" ::: "memory")

__device__ __forceinline__ void ldm_x4(uint32_t* r, uint32_t a) {
    asm volatile("ldmatrix.sync.aligned.m8n8.x4.shared.b16 {%0,%1,%2,%3}, [%4];"
        : "=r"(r[0]), "=r"(r[1]), "=r"(r[2]), "=r"(r[3]) : "r"(a));
}
__device__ __forceinline__ void ldm_x4_t(uint32_t* r, uint32_t a) {
    asm volatile("ldmatrix.sync.aligned.m8n8.x4.trans.shared.b16 {%0,%1,%2,%3}, [%4];"
        : "=r"(r[0]), "=r"(r[1]), "=r"(r[2]), "=r"(r[3]) : "r"(a));
}
__device__ __forceinline__ void mma_bf16(float* d, const uint32_t* a,
                                         uint32_t b0, uint32_t b1) {
    asm volatile(
        "mma.sync.aligned.m16n8k16.row.col.f32.bf16.bf16.f32 "
        "{%0,%1,%2,%3}, {%4,%5,%6,%7}, {%8,%9}, {%0,%1,%2,%3};"
        : "+f"(d[0]), "+f"(d[1]), "+f"(d[2]), "+f"(d[3])
        : "r"(a[0]), "r"(a[1]), "r"(a[2]), "r"(a[3]), "r"(b0), "r"(b1));
}
__device__ __forceinline__ void pack_hl(float p0, float p1, uint32_t& h, uint32_t& l) {
    __nv_bfloat16 b0 = __float2bfloat16(p0), b1 = __float2bfloat16(p1);
    h = (uint32_t)__bfloat16_as_ushort(b0) | ((uint32_t)__bfloat16_as_ushort(b1) << 16);
    __nv_bfloat16 r0 = __float2bfloat16(p0 - __bfloat162float(b0));
    __nv_bfloat16 r1 = __float2bfloat16(p1 - __bfloat162float(b1));
    l = (uint32_t)__bfloat16_as_ushort(r0) | ((uint32_t)__bfloat16_as_ushort(r1) << 16);
}

// ---------------- split fp32 -> (hi, lo) bf16 -------------------------------
__global__ __launch_bounds__(256) void split_kernel(const float* __restrict__ s,
                                                    __nv_bfloat16* __restrict__ hi,
                                                    __nv_bfloat16* __restrict__ lo,
                                                    int n4) {
    int i = blockIdx.x * blockDim.x + threadIdx.x;
    if (i >= n4) return;
    float4 v = reinterpret_cast<const float4*>(s)[i];
    ushort4 h, l;
    __nv_bfloat16 b;
    b = __float2bfloat16(v.x); h.x = __bfloat16_as_ushort(b);
    l.x = __bfloat16_as_ushort(__float2bfloat16(v.x - __bfloat162float(b)));
    b = __float2bfloat16(v.y); h.y = __bfloat16_as_ushort(b);
    l.y = __bfloat16_as_ushort(__float2bfloat16(v.y - __bfloat162float(b)));
    b = __float2bfloat16(v.z); h.z = __bfloat16_as_ushort(b);
    l.z = __bfloat16_as_ushort(__float2bfloat16(v.z - __bfloat162float(b)));
    b = __float2bfloat16(v.w); h.w = __bfloat16_as_ushort(b);
    l.w = __bfloat16_as_ushort(__float2bfloat16(v.w - __bfloat162float(b)));
    reinterpret_cast<ushort4*>(hi)[i] = h;
    reinterpret_cast<ushort4*>(lo)[i] = l;
}

// ---------------- HMMA GEMM (as R6) -----------------------------------------
#define RS     40
#define TILE_B (128 * RS * 2)
#define STG_B  (4 * TILE_B)

__global__ __launch_bounds__(256, 1) void gemm_mma(const __nv_bfloat16* __restrict__ Ah,
                                                   const __nv_bfloat16* __restrict__ Al,
                                                   const __nv_bfloat16* __restrict__ Bh,
                                                   const __nv_bfloat16* __restrict__ Bl,
                                                   const float* __restrict__ bias,
                                                   float* __restrict__ C, int MODE) {
    extern __shared__ __align__(1024) char dsm[];
    const uint32_t dsb = smem_u32(dsm);

    const int t    = threadIdx.x;
    const int lane = t & 31;
    const int wid  = t >> 5;
    const int wm   = wid & 1;
    const int wn   = wid >> 1;
    const int m0   = blockIdx.y * 128;
    const int n0   = blockIdx.x * 128;

    int      goff[2];
    uint32_t soff[2];
    #pragma unroll
    for (int i = 0; i < 2; i++) {
        int g   = t + i * 256;
        int row = g >> 2;
        int c8  = (g & 3) * 8;
        goff[i] = row * Kv + c8;
        soff[i] = (uint32_t)(row * RS + c8) * 2;
    }
    const __nv_bfloat16* Ahb = Ah + (size_t)m0 * Kv;
    const __nv_bfloat16* Alb = Al + (size_t)m0 * Kv;
    const __nv_bfloat16* Bhb = Bh + (size_t)n0 * Kv;
    const __nv_bfloat16* Blb = Bl + (size_t)n0 * Kv;

    const uint32_t a_base = dsb + (uint32_t)((wm * 64 + (lane & 15)) * RS + (lane >> 4) * 8) * 2;
    const uint32_t b_base = dsb + 2u * TILE_B
                          + (uint32_t)((wn * 32 + (lane & 15)) * RS + (lane >> 4) * 8) * 2;

    float acc[4][4][4];
    #pragma unroll
    for (int i = 0; i < 4; i++)
        #pragma unroll
        for (int n = 0; n < 4; n++)
            #pragma unroll
            for (int r = 0; r < 4; r++) acc[i][n][r] = 0.0f;

    #pragma unroll
    for (int i = 0; i < 2; i++) {
        cp16(dsb + soff[i],              Ahb + goff[i]);
        cp16(dsb + TILE_B + soff[i],     Alb + goff[i]);
        cp16(dsb + 2u*TILE_B + soff[i],  Bhb + goff[i]);
        cp16(dsb + 3u*TILE_B + soff[i],  Blb + goff[i]);
    }
    CP_COMMIT();

    const int NCHUNK = Kv / 32;
    for (int kt = 0; kt < NCHUNK; kt++) {
        const uint32_t s = (uint32_t)(kt & 1) * STG_B;
        if (kt + 1 < NCHUNK) {
            const uint32_t s1 = (uint32_t)((kt + 1) & 1) * STG_B;
            const int k1 = (kt + 1) * 32;
            #pragma unroll
            for (int i = 0; i < 2; i++) {
                cp16(dsb + s1 + soff[i],              Ahb + goff[i] + k1);
                cp16(dsb + s1 + TILE_B + soff[i],     Alb + goff[i] + k1);
                cp16(dsb + s1 + 2u*TILE_B + soff[i],  Bhb + goff[i] + k1);
                cp16(dsb + s1 + 3u*TILE_B + soff[i],  Blb + goff[i] + k1);
            }
            CP_COMMIT();
            CP_WAIT_1();
        } else {
            CP_WAIT_0();
        }
        __syncthreads();

        #pragma unroll
        for (int ks = 0; ks < 2; ks++) {
            const uint32_t ko = (uint32_t)(ks * 16) * 2;
            uint32_t ah[4][4], al[4][4];
            #pragma unroll
            for (int i = 0; i < 4; i++) {
                ldm_x4(ah[i], a_base + s + ko + (uint32_t)i * (16 * RS * 2));
                ldm_x4(al[i], a_base + s + ko + TILE_B + (uint32_t)i * (16 * RS * 2));
            }
            uint32_t bh[2][4], bl[2][4];
            #pragma unroll
            for (int j = 0; j < 2; j++) {
                ldm_x4(bh[j], b_base + s + ko + (uint32_t)j * (16 * RS * 2));
                ldm_x4(bl[j], b_base + s + ko + TILE_B + (uint32_t)j * (16 * RS * 2));
            }
            #pragma unroll
            for (int i = 0; i < 4; i++)
                #pragma unroll
                for (int n = 0; n < 4; n++) {
                    const int jp = n >> 1, jo = n & 1;
                    mma_bf16(acc[i][n], ah[i], bh[jp][jo], bh[jp][2 + jo]);
                    mma_bf16(acc[i][n], ah[i], bl[jp][jo], bl[jp][2 + jo]);
                    mma_bf16(acc[i][n], al[i], bh[jp][jo], bh[jp][2 + jo]);
                }
        }
        __syncthreads();
    }

    if (MODE == 0) {
        // scatter bf16 hi/lo into g_Q*/g_K*/g_V*
        #pragma unroll
        for (int i = 0; i < 4; i++)
            #pragma unroll
            for (int n = 0; n < 4; n++)
                #pragma unroll
                for (int r = 0; r < 4; r++) {
                    int row = m0 + wm * 64 + i * 16 + (lane >> 2) + (r >> 1) * 8;
                    int col = n0 + wn * 32 + n * 8 + (lane & 3) * 2 + (r & 1);
                    float v = acc[i][n][r] + __ldg(bias + col);
                    int bb = row >> 11;
                    int tt = row & (Tv - 1);
                    int h  = col / 192;
                    int rr = col - h * 192;
                    size_t off = (((size_t)(bb * Hv + h)) * Tv + tt) * HDv + (rr & 63);
                    __nv_bfloat16 hi = __float2bfloat16(v);
                    __nv_bfloat16 lo = __float2bfloat16(v - __bfloat162float(hi));
                    if (rr < 64)       { g_Qh[off] = hi; g_Ql[off] = lo; }
                    else if (rr < 128) { g_Kh[off] = hi; g_Kl[off] = lo; }
                    else               { g_Vh[off] = hi; g_Vl[off] = lo; }
                }
    } else {
        #pragma unroll
        for (int i = 0; i < 4; i++)
            #pragma unroll
            for (int n = 0; n < 4; n++) {
                int row = m0 + wm * 64 + i * 16 + (lane >> 2);
                int col = n0 + wn * 32 + n * 8 + (lane & 3) * 2;
                float b0 = __ldg(bias + col), b1 = __ldg(bias + col + 1);
                float2 v0 = make_float2(acc[i][n][0] + b0, acc[i][n][1] + b1);
                float2 v1 = make_float2(acc[i][n][2] + b0, acc[i][n][3] + b1);
                *reinterpret_cast<float2*>(C + (size_t)row * Dv + col)       = v0;
                *reinterpret_cast<float2*>(C + (size_t)(row + 8) * Dv + col) = v1;
            }
    }
}

// ---------------- flash attention, HMMA split-precision ---------------------
// CTA: 128 queries x 64-key tiles, 8 warps (warp = 16 q-rows x all 64 keys).
// S = QhKh + QhKl + QlKh ; O += PhVh + PhVl + PlVh (all fp32 accum).
#define FRS        72                       // SMEM row stride (bf16 elems)
#define FQ_TILE_B  (128 * FRS * 2)          // 18432
#define FK_TILE_B  (64 * FRS * 2)           // 9216
#define FST_B      (4 * FK_TILE_B)          // 36864 per stage (Kh,Kl,Vh,Vl)
#define FLASH_SMEM (2 * FQ_TILE_B + 2 * FST_B)  // 110592

__global__ __launch_bounds__(256, 1) void flash_mma() {
    extern __shared__ __align__(1024) char fsm[];
    const uint32_t base = smem_u32(fsm);

    const int t    = threadIdx.x;
    const int lane = t & 31;
    const int wid  = t >> 5;
    const int bh   = blockIdx.y;
    const int qt   = blockIdx.x;
    const int q0   = qt * 128;
    const int NKT  = 2 * qt + 2;

    const __nv_bfloat16* Qhg = g_Qh + ((size_t)bh * Tv + q0) * HDv;
    const __nv_bfloat16* Qlg = g_Ql + ((size_t)bh * Tv + q0) * HDv;
    const __nv_bfloat16* Khg = g_Kh + (size_t)bh * Tv * HDv;
    const __nv_bfloat16* Klg = g_Kl + (size_t)bh * Tv * HDv;
    const __nv_bfloat16* Vhg = g_Vh + (size_t)bh * Tv * HDv;
    const __nv_bfloat16* Vlg = g_Vl + (size_t)bh * Tv * HDv;

    // ---- issue Q (group 0) ----
    #pragma unroll
    for (int i = 0; i < 4; i++) {
        int g = t + i * 256;          // 0..1023
        int r = g >> 3;
        int c8 = (g & 7) * 8;
        uint32_t so = (uint32_t)(r * FRS + c8) * 2;
        cp16(base + so,             Qhg + r * HDv + c8);
        cp16(base + FQ_TILE_B + so, Qlg + r * HDv + c8);
    }
    CP_COMMIT();
    // ---- issue stage 0 (group 1) ----
    {
        int g = t, r = g >> 3, c8 = (g & 7) * 8;
        int g2 = t + 256, r2 = g2 >> 3, c82 = (g2 & 7) * 8;
        uint32_t st = base + 2 * FQ_TILE_B;
        uint32_t so  = (uint32_t)(r  * FRS + c8)  * 2;
        uint32_t so2 = (uint32_t)(r2 * FRS + c82) * 2;
        int go  = r  * HDv + c8;
        int go2 = r2 * HDv + c82;
        cp16(st + so,                 Khg + go);  cp16(st + so2,                 Khg + go2);
        cp16(st + FK_TILE_B + so,     Klg + go);  cp16(st + FK_TILE_B + so2,     Klg + go2);
        cp16(st + 2*FK_TILE_B + so,   Vhg + go);  cp16(st + 2*FK_TILE_B + so2,   Vhg + go2);
        cp16(st + 3*FK_TILE_B + so,   Vlg + go);  cp16(st + 3*FK_TILE_B + so2,   Vlg + go2);
    }
    CP_COMMIT();

    const int qw0 = q0 + wid * 16;
    float m_[2] = {-INFINITY, -INFINITY};
    float l_[2] = {0.0f, 0.0f};
    float o[8][4];
    #pragma unroll
    for (int n = 0; n < 8; n++)
        #pragma unroll
        for (int e = 0; e < 4; e++) o[n][e] = 0.0f;

    uint32_t qh[4][4], ql[4][4];

    // ldmatrix address bases
    const uint32_t q_lmb = base + (uint32_t)((wid * 16 + (lane & 15)) * FRS + (lane >> 4) * 8) * 2;
    const uint32_t k_lane = (uint32_t)((lane & 15) * FRS + (lane >> 4) * 8) * 2;
    const uint32_t v_lane = (uint32_t)(((lane & 7) + ((lane >> 4) << 3)) * FRS + ((lane >> 3) & 1) * 8) * 2;

    for (int kt = 0; kt < NKT; kt++) {
        const uint32_t st = base + 2 * FQ_TILE_B + (uint32_t)(kt & 1) * FST_B;
        if (kt + 1 < NKT) {
            const uint32_t st1 = base + 2 * FQ_TILE_B + (uint32_t)((kt + 1) & 1) * FST_B;
            const int kr = (kt + 1) * 64;
            int g = t, r = g >> 3, c8 = (g & 7) * 8;
            int g2 = t + 256, r2 = g2 >> 3, c82 = (g2 & 7) * 8;
            uint32_t so  = (uint32_t)(r  * FRS + c8)  * 2;
            uint32_t so2 = (uint32_t)(r2 * FRS + c82) * 2;
            int go  = (kr + r)  * HDv + c8;
            int go2 = (kr + r2) * HDv + c82;
            cp16(st1 + so,               Khg + go);  cp16(st1 + so2,               Khg + go2);
            cp16(st1 + FK_TILE_B + so,   Klg + go);  cp16(st1 + FK_TILE_B + so2,   Klg + go2);
            cp16(st1 + 2*FK_TILE_B + so, Vhg + go);  cp16(st1 + 2*FK_TILE_B + so2, Vhg + go2);
            cp16(st1 + 3*FK_TILE_B + so, Vlg + go);  cp16(st1 + 3*FK_TILE_B + so2, Vlg + go2);
            CP_COMMIT();
            CP_WAIT_1();
        } else {
            CP_WAIT_0();
        }
        __syncthreads();

        if (kt == 0) {
            #pragma unroll
            for (int kg = 0; kg < 4; kg++) {
                ldm_x4(qh[kg], q_lmb + kg * 32);
                ldm_x4(ql[kg], q_lmb + FQ_TILE_B + kg * 32);
            }
        }

        const int k0 = kt * 64;
        if (k0 <= qw0 + 15) {
            // ---- S = Q K^T (split) ----
            float sa[8][4];
            #pragma unroll
            for (int n = 0; n < 8; n++)
                #pragma unroll
                for (int e = 0; e < 4; e++) sa[n][e] = 0.0f;

            #pragma unroll
            for (int kg = 0; kg < 4; kg++) {
                #pragma unroll
                for (int np = 0; np < 4; np++) {
                    uint32_t addr = st + k_lane + (uint32_t)(np * 16 * FRS * 2) + kg * 32;
                    uint32_t kb[4], kl[4];
                    ldm_x4(kb, addr);
                    ldm_x4(kl, addr + FK_TILE_B);
                    mma_bf16(sa[2*np],   qh[kg], kb[0], kb[2]);
                    mma_bf16(sa[2*np+1], qh[kg], kb[1], kb[3]);
                    mma_bf16(sa[2*np],   qh[kg], kl[0], kl[2]);
                    mma_bf16(sa[2*np+1], qh[kg], kl[1], kl[3]);
                    mma_bf16(sa[2*np],   ql[kg], kb[0], kb[2]);
                    mma_bf16(sa[2*np+1], ql[kg], kb[1], kb[3]);
                }
            }

            // ---- scale + causal mask ----
            const int r0 = qw0 + (lane >> 2);
            #pragma unroll
            for (int n = 0; n < 8; n++)
                #pragma unroll
                for (int e = 0; e < 4; e++) {
                    float v = sa[n][e] * 0.125f;
                    int rr = r0 + (e >> 1) * 8;
                    int cc = k0 + n * 8 + (lane & 3) * 2 + (e & 1);
                    sa[n][e] = (cc > rr) ? -INFINITY : v;
                }

            // ---- online softmax (2 rows per lane) ----
            float corr[2];
            #pragma unroll
            for (int rh = 0; rh < 2; rh++) {
                float mx = -INFINITY;
                #pragma unroll
                for (int n = 0; n < 8; n++)
                    mx = fmaxf(mx, fmaxf(sa[n][2*rh], sa[n][2*rh+1]));
                mx = fmaxf(mx, __shfl_xor_sync(0xffffffffu, mx, 1));
                mx = fmaxf(mx, __shfl_xor_sync(0xffffffffu, mx, 2));
                float mnew = fmaxf(m_[rh], mx);
                corr[rh] = __expf(m_[rh] - mnew);
                m_[rh] = mnew;
                float rs = 0.0f;
                #pragma unroll
                for (int n = 0; n < 8; n++) {
                    float p0 = __expf(sa[n][2*rh]   - mnew);
                    float p1 = __expf(sa[n][2*rh+1] - mnew);
                    sa[n][2*rh] = p0; sa[n][2*rh+1] = p1;
                    rs += p0 + p1;
                }
                rs += __shfl_xor_sync(0xffffffffu, rs, 1);
                rs += __shfl_xor_sync(0xffffffffu, rs, 2);
                l_[rh] = l_[rh] * corr[rh] + rs;
            }
            #pragma unroll
            for (int n = 0; n < 8; n++) {
                o[n][0] *= corr[0]; o[n][1] *= corr[0];
                o[n][2] *= corr[1]; o[n][3] *= corr[1];
            }

            // ---- O += P V (split) ----
            #pragma unroll
            for (int kg = 0; kg < 4; kg++) {
                uint32_t pah[4], pal[4];
                pack_hl(sa[2*kg][0],   sa[2*kg][1],   pah[0], pal[0]);
                pack_hl(sa[2*kg][2],   sa[2*kg][3],   pah[1], pal[1]);
                pack_hl(sa[2*kg+1][0], sa[2*kg+1][1], pah[2], pal[2]);
                pack_hl(sa[2*kg+1][2], sa[2*kg+1][3], pah[3], pal[3]);
                #pragma unroll
                for (int ndp = 0; ndp < 4; ndp++) {
                    uint32_t addr = st + 2*FK_TILE_B + v_lane
                                  + (uint32_t)(kg * 16 * FRS * 2) + ndp * 32;
                    uint32_t vb[4], vl[4];
                    ldm_x4_t(vb, addr);
                    ldm_x4_t(vl, addr + FK_TILE_B);
                    mma_bf16(o[2*ndp],   pah, vb[0], vb[2]);
                    mma_bf16(o[2*ndp+1], pah, vb[1], vb[3]);
                    mma_bf16(o[2*ndp],   pah, vl[0], vl[2]);
                    mma_bf16(o[2*ndp+1], pah, vl[1], vl[3]);
                    mma_bf16(o[2*ndp],   pal, vb[0], vb[2]);
                    mma_bf16(o[2*ndp+1], pal, vb[1], vb[3]);
                }
            }
        }
        __syncthreads();
    }

    // ---- finalize: O /= l, write g_Att [B,T,D] ----
    const int bb = bh >> 4;
    const int h  = bh & 15;
    const float i0 = 1.0f / l_[0], i1 = 1.0f / l_[1];
    const int row = q0 + wid * 16 + (lane >> 2);
    #pragma unroll
    for (int nd = 0; nd < 8; nd++) {
        int col = h * 64 + nd * 8 + (lane & 3) * 2;
        float2 v0 = make_float2(o[nd][0] * i0, o[nd][1] * i0);
        float2 v1 = make_float2(o[nd][2] * i1, o[nd][3] * i1);
        *reinterpret_cast<float2*>(g_Att + ((size_t)(bb * Tv) + row)     * Dv + col) = v0;
        *reinterpret_cast<float2*>(g_Att + ((size_t)(bb * Tv) + row + 8) * Dv + col) = v1;
    }
}

// ---------------------------------------------------------------------------
extern "C" void kernel_launch(void* const* d_in, const int* in_sizes, int n_in,
                              void* d_out, int out_size) {
    const float* x    = (const float*)d_in[0];
    const float* Wqkv = (const float*)d_in[1];
    const float* bqkv = (const float*)d_in[2];
    const float* Wout = (const float*)d_in[3];
    const float* bout = (const float*)d_in[4];
    float* out = (float*)d_out;

    void *xh, *xl, *wqh, *wql, *ah, *al, *woh, *wol, *attp;
    cudaGetSymbolAddress(&xh,  g_xh);  cudaGetSymbolAddress(&xl,  g_xl);
    cudaGetSymbolAddress(&wqh, g_wqh); cudaGetSymbolAddress(&wql, g_wql);
    cudaGetSymbolAddress(&ah,  g_ah);  cudaGetSymbolAddress(&al,  g_al);
    cudaGetSymbolAddress(&woh, g_woh); cudaGetSymbolAddress(&wol, g_wol);
    cudaGetSymbolAddress(&attp, g_Att);

    cudaFuncSetAttribute(gemm_mma,  cudaFuncAttributeMaxDynamicSharedMemorySize, 2 * STG_B);
    cudaFuncSetAttribute(flash_mma, cudaFuncAttributeMaxDynamicSharedMemorySize, FLASH_SMEM);

    split_kernel<<<Mv * Kv / 1024, 256>>>(x, (__nv_bfloat16*)xh, (__nv_bfloat16*)xl, Mv * Kv / 4);
    split_kernel<<<QKV_N * Kv / 1024, 256>>>(Wqkv, (__nv_bfloat16*)wqh, (__nv_bfloat16*)wql, QKV_N * Kv / 4);
    split_kernel<<<Dv * Kv / 1024, 256>>>(Wout, (__nv_bfloat16*)woh, (__nv_bfloat16*)wol, Dv * Kv / 4);

    // 1) QKV projection -> bf16 hi/lo Q,K,V
    gemm_mma<<<dim3(QKV_N / 128, Mv / 128), 256, 2 * STG_B>>>(
        (__nv_bfloat16*)xh, (__nv_bfloat16*)xl, (__nv_bfloat16*)wqh, (__nv_bfloat16*)wql,
        bqkv, nullptr, 0);

    // 2) causal flash attention on tensor cores
    flash_mma<<<dim3(Tv / 128, Bv * Hv), 256, FLASH_SMEM>>>();

    // 3) split attention output, output projection
    split_kernel<<<Mv * Dv / 1024, 256>>>((const float*)attp, (__nv_bfloat16*)ah, (__nv_bfloat16*)al, Mv * Dv / 4);
    gemm_mma<<<dim3(Dv / 128, Mv / 128), 256, 2 * STG_B>>>(
        (__nv_bfloat16*)ah, (__nv_bfloat16*)al, (__nv_bfloat16*)woh, (__nv_bfloat16*)wol,
        bout, out, 1);
}

// round 8
// speedup vs baseline: 2.3892x; 1.1001x over previous
#include <cuda_runtime.h>
#include <cuda_bf16.h>
#include <math.h>
#include <stdint.h>

#define Bv 2
#define Tv 2048
#define Dv 1024
#define Hv 16
#define HDv 64
#define Mv 4096          // B*T
#define Kv 1024
#define QKV_N 3072

// ---------------- device scratch (no allocations allowed) ------------------
__device__ __align__(16) float g_Att[Mv*Dv];

__device__ __align__(16) __nv_bfloat16 g_Qh[Bv*Hv*Tv*HDv], g_Ql[Bv*Hv*Tv*HDv];
__device__ __align__(16) __nv_bfloat16 g_Kh[Bv*Hv*Tv*HDv], g_Kl[Bv*Hv*Tv*HDv];
__device__ __align__(16) __nv_bfloat16 g_Vh[Bv*Hv*Tv*HDv], g_Vl[Bv*Hv*Tv*HDv];

__device__ __align__(16) __nv_bfloat16 g_xh[Mv*Kv],     g_xl[Mv*Kv];
__device__ __align__(16) __nv_bfloat16 g_wqh[QKV_N*Kv], g_wql[QKV_N*Kv];
__device__ __align__(16) __nv_bfloat16 g_ah[Mv*Kv],     g_al[Mv*Kv];
__device__ __align__(16) __nv_bfloat16 g_woh[Dv*Kv],    g_wol[Dv*Kv];

// ---------------- PTX helpers ------------------------------------------------
__device__ __forceinline__ uint32_t smem_u32(const void* p) {
    uint32_t a;
    asm("{ .reg .u64 t; cvta.to.shared.u64 t, %1; cvt.u32.u64 %0, t; }" : "=r"(a) : "l"(p));
    return a;
}
__device__ __forceinline__ void cp16(uint32_t s, const void* g) {
    asm volatile("cp.async.cg.shared.global [%0], [%1], 16;" :: "r"(s), "l"(g));
}
#define CP_COMMIT()  asm volatile("cp.async.commit_group;" ::: "memory")
#define CP_WAIT_1()  asm volatile("cp.async.wait_group 1;" ::: "memory")
#define CP_WAIT_0()  asm volatile("cp.async.wait_group 0;" ::: "memory")

__device__ __forceinline__ void ldm_x4(uint32_t* r, uint32_t a) {
    asm volatile("ldmatrix.sync.aligned.m8n8.x4.shared.b16 {%0,%1,%2,%3}, [%4];"
        : "=r"(r[0]), "=r"(r[1]), "=r"(r[2]), "=r"(r[3]) : "r"(a));
}
__device__ __forceinline__ void ldm_x4_t(uint32_t* r, uint32_t a) {
    asm volatile("ldmatrix.sync.aligned.m8n8.x4.trans.shared.b16 {%0,%1,%2,%3}, [%4];"
        : "=r"(r[0]), "=r"(r[1]), "=r"(r[2]), "=r"(r[3]) : "r"(a));
}
__device__ __forceinline__ void mma_bf16(float* d, const uint32_t* a,
                                         uint32_t b0, uint32_t b1) {
    asm volatile(
        "mma.sync.aligned.m16n8k16.row.col.f32.bf16.bf16.f32 "
        "{%0,%1,%2,%3}, {%4,%5,%6,%7}, {%8,%9}, {%0,%1,%2,%3};"
        : "+f"(d[0]), "+f"(d[1]), "+f"(d[2]), "+f"(d[3])
        : "r"(a[0]), "r"(a[1]), "r"(a[2]), "r"(a[3]), "r"(b0), "r"(b1));
}
__device__ __forceinline__ void pack_hl(float p0, float p1, uint32_t& h, uint32_t& l) {
    __nv_bfloat16 b0 = __float2bfloat16(p0), b1 = __float2bfloat16(p1);
    h = (uint32_t)__bfloat16_as_ushort(b0) | ((uint32_t)__bfloat16_as_ushort(b1) << 16);
    __nv_bfloat16 r0 = __float2bfloat16(p0 - __bfloat162float(b0));
    __nv_bfloat16 r1 = __float2bfloat16(p1 - __bfloat162float(b1));
    l = (uint32_t)__bfloat16_as_ushort(r0) | ((uint32_t)__bfloat16_as_ushort(r1) << 16);
}

// ---------------- split fp32 -> (hi, lo) bf16 -------------------------------
__global__ __launch_bounds__(256) void split_kernel(const float* __restrict__ s,
                                                    __nv_bfloat16* __restrict__ hi,
                                                    __nv_bfloat16* __restrict__ lo,
                                                    int n4) {
    int i = blockIdx.x * blockDim.x + threadIdx.x;
    if (i >= n4) return;
    float4 v = reinterpret_cast<const float4*>(s)[i];
    ushort4 h, l;
    __nv_bfloat16 b;
    b = __float2bfloat16(v.x); h.x = __bfloat16_as_ushort(b);
    l.x = __bfloat16_as_ushort(__float2bfloat16(v.x - __bfloat162float(b)));
    b = __float2bfloat16(v.y); h.y = __bfloat16_as_ushort(b);
    l.y = __bfloat16_as_ushort(__float2bfloat16(v.y - __bfloat162float(b)));
    b = __float2bfloat16(v.z); h.z = __bfloat16_as_ushort(b);
    l.z = __bfloat16_as_ushort(__float2bfloat16(v.z - __bfloat162float(b)));
    b = __float2bfloat16(v.w); h.w = __bfloat16_as_ushort(b);
    l.w = __bfloat16_as_ushort(__float2bfloat16(v.w - __bfloat162float(b)));
    reinterpret_cast<ushort4*>(hi)[i] = h;
    reinterpret_cast<ushort4*>(lo)[i] = l;
}

// ---------------- HMMA GEMM (pass-major MMA issue) --------------------------
#define RS     40
#define TILE_B (128 * RS * 2)
#define STG_B  (4 * TILE_B)

__global__ __launch_bounds__(256, 1) void gemm_mma(const __nv_bfloat16* __restrict__ Ah,
                                                   const __nv_bfloat16* __restrict__ Al,
                                                   const __nv_bfloat16* __restrict__ Bh,
                                                   const __nv_bfloat16* __restrict__ Bl,
                                                   const float* __restrict__ bias,
                                                   float* __restrict__ C, int MODE) {
    extern __shared__ __align__(1024) char dsm[];
    const uint32_t dsb = smem_u32(dsm);

    const int t    = threadIdx.x;
    const int lane = t & 31;
    const int wid  = t >> 5;
    const int wm   = wid & 1;
    const int wn   = wid >> 1;
    const int m0   = blockIdx.y * 128;
    const int n0   = blockIdx.x * 128;

    int      goff[2];
    uint32_t soff[2];
    #pragma unroll
    for (int i = 0; i < 2; i++) {
        int g   = t + i * 256;
        int row = g >> 2;
        int c8  = (g & 3) * 8;
        goff[i] = row * Kv + c8;
        soff[i] = (uint32_t)(row * RS + c8) * 2;
    }
    const __nv_bfloat16* Ahb = Ah + (size_t)m0 * Kv;
    const __nv_bfloat16* Alb = Al + (size_t)m0 * Kv;
    const __nv_bfloat16* Bhb = Bh + (size_t)n0 * Kv;
    const __nv_bfloat16* Blb = Bl + (size_t)n0 * Kv;

    const uint32_t a_base = dsb + (uint32_t)((wm * 64 + (lane & 15)) * RS + (lane >> 4) * 8) * 2;
    const uint32_t b_base = dsb + 2u * TILE_B
                          + (uint32_t)((wn * 32 + (lane & 15)) * RS + (lane >> 4) * 8) * 2;

    float acc[4][4][4];
    #pragma unroll
    for (int i = 0; i < 4; i++)
        #pragma unroll
        for (int n = 0; n < 4; n++)
            #pragma unroll
            for (int r = 0; r < 4; r++) acc[i][n][r] = 0.0f;

    #pragma unroll
    for (int i = 0; i < 2; i++) {
        cp16(dsb + soff[i],              Ahb + goff[i]);
        cp16(dsb + TILE_B + soff[i],     Alb + goff[i]);
        cp16(dsb + 2u*TILE_B + soff[i],  Bhb + goff[i]);
        cp16(dsb + 3u*TILE_B + soff[i],  Blb + goff[i]);
    }
    CP_COMMIT();

    const int NCHUNK = Kv / 32;
    for (int kt = 0; kt < NCHUNK; kt++) {
        const uint32_t s = (uint32_t)(kt & 1) * STG_B;
        if (kt + 1 < NCHUNK) {
            const uint32_t s1 = (uint32_t)((kt + 1) & 1) * STG_B;
            const int k1 = (kt + 1) * 32;
            #pragma unroll
            for (int i = 0; i < 2; i++) {
                cp16(dsb + s1 + soff[i],              Ahb + goff[i] + k1);
                cp16(dsb + s1 + TILE_B + soff[i],     Alb + goff[i] + k1);
                cp16(dsb + s1 + 2u*TILE_B + soff[i],  Bhb + goff[i] + k1);
                cp16(dsb + s1 + 3u*TILE_B + soff[i],  Blb + goff[i] + k1);
            }
            CP_COMMIT();
            CP_WAIT_1();
        } else {
            CP_WAIT_0();
        }
        __syncthreads();

        #pragma unroll
        for (int ks = 0; ks < 2; ks++) {
            const uint32_t ko = (uint32_t)(ks * 16) * 2;
            uint32_t ah[4][4], al[4][4];
            #pragma unroll
            for (int i = 0; i < 4; i++) {
                ldm_x4(ah[i], a_base + s + ko + (uint32_t)i * (16 * RS * 2));
                ldm_x4(al[i], a_base + s + ko + TILE_B + (uint32_t)i * (16 * RS * 2));
            }
            uint32_t bh[2][4], bl[2][4];
            #pragma unroll
            for (int j = 0; j < 2; j++) {
                ldm_x4(bh[j], b_base + s + ko + (uint32_t)j * (16 * RS * 2));
                ldm_x4(bl[j], b_base + s + ko + TILE_B + (uint32_t)j * (16 * RS * 2));
            }
            // pass-major: 16 independent MMAs per pass (no back-to-back acc reuse)
            #pragma unroll
            for (int i = 0; i < 4; i++)
                #pragma unroll
                for (int n = 0; n < 4; n++) {
                    const int jp = n >> 1, jo = n & 1;
                    mma_bf16(acc[i][n], ah[i], bh[jp][jo], bh[jp][2 + jo]);   // hi*hi
                }
            #pragma unroll
            for (int i = 0; i < 4; i++)
                #pragma unroll
                for (int n = 0; n < 4; n++) {
                    const int jp = n >> 1, jo = n & 1;
                    mma_bf16(acc[i][n], ah[i], bl[jp][jo], bl[jp][2 + jo]);   // hi*lo
                }
            #pragma unroll
            for (int i = 0; i < 4; i++)
                #pragma unroll
                for (int n = 0; n < 4; n++) {
                    const int jp = n >> 1, jo = n & 1;
                    mma_bf16(acc[i][n], al[i], bh[jp][jo], bh[jp][2 + jo]);   // lo*hi
                }
        }
        __syncthreads();
    }

    if (MODE == 0) {
        #pragma unroll
        for (int i = 0; i < 4; i++)
            #pragma unroll
            for (int n = 0; n < 4; n++)
                #pragma unroll
                for (int r = 0; r < 4; r++) {
                    int row = m0 + wm * 64 + i * 16 + (lane >> 2) + (r >> 1) * 8;
                    int col = n0 + wn * 32 + n * 8 + (lane & 3) * 2 + (r & 1);
                    float v = acc[i][n][r] + __ldg(bias + col);
                    int bb = row >> 11;
                    int tt = row & (Tv - 1);
                    int h  = col / 192;
                    int rr = col - h * 192;
                    size_t off = (((size_t)(bb * Hv + h)) * Tv + tt) * HDv + (rr & 63);
                    __nv_bfloat16 hi = __float2bfloat16(v);
                    __nv_bfloat16 lo = __float2bfloat16(v - __bfloat162float(hi));
                    if (rr < 64)       { g_Qh[off] = hi; g_Ql[off] = lo; }
                    else if (rr < 128) { g_Kh[off] = hi; g_Kl[off] = lo; }
                    else               { g_Vh[off] = hi; g_Vl[off] = lo; }
                }
    } else {
        #pragma unroll
        for (int i = 0; i < 4; i++)
            #pragma unroll
            for (int n = 0; n < 4; n++) {
                int row = m0 + wm * 64 + i * 16 + (lane >> 2);
                int col = n0 + wn * 32 + n * 8 + (lane & 3) * 2;
                float b0 = __ldg(bias + col), b1 = __ldg(bias + col + 1);
                float2 v0 = make_float2(acc[i][n][0] + b0, acc[i][n][1] + b1);
                float2 v1 = make_float2(acc[i][n][2] + b0, acc[i][n][3] + b1);
                *reinterpret_cast<float2*>(C + (size_t)row * Dv + col)       = v0;
                *reinterpret_cast<float2*>(C + (size_t)(row + 8) * Dv + col) = v1;
            }
    }
}

// ---------------- flash attention, HMMA split-precision ---------------------
#define FRS        72
#define FQ_TILE_B  (128 * FRS * 2)
#define FK_TILE_B  (64 * FRS * 2)
#define FST_B      (4 * FK_TILE_B)
#define FLASH_SMEM (2 * FQ_TILE_B + 2 * FST_B)

__global__ __launch_bounds__(256, 1) void flash_mma() {
    extern __shared__ __align__(1024) char fsm[];
    const uint32_t base = smem_u32(fsm);

    const int t    = threadIdx.x;
    const int lane = t & 31;
    const int wid  = t >> 5;
    const int bh   = blockIdx.y;
    const int qt   = blockIdx.x;
    const int q0   = qt * 128;
    const int NKT  = 2 * qt + 2;

    const __nv_bfloat16* Qhg = g_Qh + ((size_t)bh * Tv + q0) * HDv;
    const __nv_bfloat16* Qlg = g_Ql + ((size_t)bh * Tv + q0) * HDv;
    const __nv_bfloat16* Khg = g_Kh + (size_t)bh * Tv * HDv;
    const __nv_bfloat16* Klg = g_Kl + (size_t)bh * Tv * HDv;
    const __nv_bfloat16* Vhg = g_Vh + (size_t)bh * Tv * HDv;
    const __nv_bfloat16* Vlg = g_Vl + (size_t)bh * Tv * HDv;

    #pragma unroll
    for (int i = 0; i < 4; i++) {
        int g = t + i * 256;
        int r = g >> 3;
        int c8 = (g & 7) * 8;
        uint32_t so = (uint32_t)(r * FRS + c8) * 2;
        cp16(base + so,             Qhg + r * HDv + c8);
        cp16(base + FQ_TILE_B + so, Qlg + r * HDv + c8);
    }
    CP_COMMIT();
    {
        int g = t, r = g >> 3, c8 = (g & 7) * 8;
        int g2 = t + 256, r2 = g2 >> 3, c82 = (g2 & 7) * 8;
        uint32_t st = base + 2 * FQ_TILE_B;
        uint32_t so  = (uint32_t)(r  * FRS + c8)  * 2;
        uint32_t so2 = (uint32_t)(r2 * FRS + c82) * 2;
        int go  = r  * HDv + c8;
        int go2 = r2 * HDv + c82;
        cp16(st + so,                 Khg + go);  cp16(st + so2,                 Khg + go2);
        cp16(st + FK_TILE_B + so,     Klg + go);  cp16(st + FK_TILE_B + so2,     Klg + go2);
        cp16(st + 2*FK_TILE_B + so,   Vhg + go);  cp16(st + 2*FK_TILE_B + so2,   Vhg + go2);
        cp16(st + 3*FK_TILE_B + so,   Vlg + go);  cp16(st + 3*FK_TILE_B + so2,   Vlg + go2);
    }
    CP_COMMIT();

    const int qw0 = q0 + wid * 16;
    float m_[2] = {-INFINITY, -INFINITY};
    float l_[2] = {0.0f, 0.0f};
    float o[8][4];
    #pragma unroll
    for (int n = 0; n < 8; n++)
        #pragma unroll
        for (int e = 0; e < 4; e++) o[n][e] = 0.0f;

    uint32_t qh[4][4], ql[4][4];

    const uint32_t q_lmb = base + (uint32_t)((wid * 16 + (lane & 15)) * FRS + (lane >> 4) * 8) * 2;
    const uint32_t k_lane = (uint32_t)((lane & 15) * FRS + (lane >> 4) * 8) * 2;
    const uint32_t v_lane = (uint32_t)(((lane & 7) + ((lane >> 4) << 3)) * FRS + ((lane >> 3) & 1) * 8) * 2;

    for (int kt = 0; kt < NKT; kt++) {
        const uint32_t st = base + 2 * FQ_TILE_B + (uint32_t)(kt & 1) * FST_B;
        if (kt + 1 < NKT) {
            const uint32_t st1 = base + 2 * FQ_TILE_B + (uint32_t)((kt + 1) & 1) * FST_B;
            const int kr = (kt + 1) * 64;
            int g = t, r = g >> 3, c8 = (g & 7) * 8;
            int g2 = t + 256, r2 = g2 >> 3, c82 = (g2 & 7) * 8;
            uint32_t so  = (uint32_t)(r  * FRS + c8)  * 2;
            uint32_t so2 = (uint32_t)(r2 * FRS + c82) * 2;
            int go  = (kr + r)  * HDv + c8;
            int go2 = (kr + r2) * HDv + c82;
            cp16(st1 + so,               Khg + go);  cp16(st1 + so2,               Khg + go2);
            cp16(st1 + FK_TILE_B + so,   Klg + go);  cp16(st1 + FK_TILE_B + so2,   Klg + go2);
            cp16(st1 + 2*FK_TILE_B + so, Vhg + go);  cp16(st1 + 2*FK_TILE_B + so2, Vhg + go2);
            cp16(st1 + 3*FK_TILE_B + so, Vlg + go);  cp16(st1 + 3*FK_TILE_B + so2, Vlg + go2);
            CP_COMMIT();
            CP_WAIT_1();
        } else {
            CP_WAIT_0();
        }
        __syncthreads();

        if (kt == 0) {
            #pragma unroll
            for (int kg = 0; kg < 4; kg++) {
                ldm_x4(qh[kg], q_lmb + kg * 32);
                ldm_x4(ql[kg], q_lmb + FQ_TILE_B + kg * 32);
            }
        }

        const int k0 = kt * 64;
        if (k0 <= qw0 + 15) {
            // ---- S = Q K^T (split, pass-major) ----
            float sa[8][4];
            #pragma unroll
            for (int n = 0; n < 8; n++)
                #pragma unroll
                for (int e = 0; e < 4; e++) sa[n][e] = 0.0f;

            #pragma unroll
            for (int kg = 0; kg < 4; kg++) {
                uint32_t kb[4][4], kl[4][4];
                #pragma unroll
                for (int np = 0; np < 4; np++) {
                    uint32_t addr = st + k_lane + (uint32_t)(np * 16 * FRS * 2) + kg * 32;
                    ldm_x4(kb[np], addr);
                    ldm_x4(kl[np], addr + FK_TILE_B);
                }
                #pragma unroll
                for (int np = 0; np < 4; np++) {      // hi*hi: 8 independent
                    mma_bf16(sa[2*np],   qh[kg], kb[np][0], kb[np][2]);
                    mma_bf16(sa[2*np+1], qh[kg], kb[np][1], kb[np][3]);
                }
                #pragma unroll
                for (int np = 0; np < 4; np++) {      // hi*lo
                    mma_bf16(sa[2*np],   qh[kg], kl[np][0], kl[np][2]);
                    mma_bf16(sa[2*np+1], qh[kg], kl[np][1], kl[np][3]);
                }
                #pragma unroll
                for (int np = 0; np < 4; np++) {      // lo*hi
                    mma_bf16(sa[2*np],   ql[kg], kb[np][0], kb[np][2]);
                    mma_bf16(sa[2*np+1], ql[kg], kb[np][1], kb[np][3]);
                }
            }

            // ---- scale + causal mask ----
            const int r0 = qw0 + (lane >> 2);
            #pragma unroll
            for (int n = 0; n < 8; n++)
                #pragma unroll
                for (int e = 0; e < 4; e++) {
                    float v = sa[n][e] * 0.125f;
                    int rr = r0 + (e >> 1) * 8;
                    int cc = k0 + n * 8 + (lane & 3) * 2 + (e & 1);
                    sa[n][e] = (cc > rr) ? -INFINITY : v;
                }

            // ---- online softmax ----
            float corr[2];
            #pragma unroll
            for (int rh = 0; rh < 2; rh++) {
                float mx = -INFINITY;
                #pragma unroll
                for (int n = 0; n < 8; n++)
                    mx = fmaxf(mx, fmaxf(sa[n][2*rh], sa[n][2*rh+1]));
                mx = fmaxf(mx, __shfl_xor_sync(0xffffffffu, mx, 1));
                mx = fmaxf(mx, __shfl_xor_sync(0xffffffffu, mx, 2));
                float mnew = fmaxf(m_[rh], mx);
                corr[rh] = __expf(m_[rh] - mnew);
                m_[rh] = mnew;
                float rs = 0.0f;
                #pragma unroll
                for (int n = 0; n < 8; n++) {
                    float p0 = __expf(sa[n][2*rh]   - mnew);
                    float p1 = __expf(sa[n][2*rh+1] - mnew);
                    sa[n][2*rh] = p0; sa[n][2*rh+1] = p1;
                    rs += p0 + p1;
                }
                rs += __shfl_xor_sync(0xffffffffu, rs, 1);
                rs += __shfl_xor_sync(0xffffffffu, rs, 2);
                l_[rh] = l_[rh] * corr[rh] + rs;
            }
            #pragma unroll
            for (int n = 0; n < 8; n++) {
                o[n][0] *= corr[0]; o[n][1] *= corr[0];
                o[n][2] *= corr[1]; o[n][3] *= corr[1];
            }

            // ---- O += P V (split, pass-major) ----
            #pragma unroll
            for (int kg = 0; kg < 4; kg++) {
                uint32_t pah[4], pal[4];
                pack_hl(sa[2*kg][0],   sa[2*kg][1],   pah[0], pal[0]);
                pack_hl(sa[2*kg][2],   sa[2*kg][3],   pah[1], pal[1]);
                pack_hl(sa[2*kg+1][0], sa[2*kg+1][1], pah[2], pal[2]);
                pack_hl(sa[2*kg+1][2], sa[2*kg+1][3], pah[3], pal[3]);
                uint32_t vb[4][4], vl[4][4];
                #pragma unroll
                for (int ndp = 0; ndp < 4; ndp++) {
                    uint32_t addr = st + 2*FK_TILE_B + v_lane
                                  + (uint32_t)(kg * 16 * FRS * 2) + ndp * 32;
                    ldm_x4_t(vb[ndp], addr);
                    ldm_x4_t(vl[ndp], addr + FK_TILE_B);
                }
                #pragma unroll
                for (int ndp = 0; ndp < 4; ndp++) {   // Ph*Vh: 8 independent
                    mma_bf16(o[2*ndp],   pah, vb[ndp][0], vb[ndp][2]);
                    mma_bf16(o[2*ndp+1], pah, vb[ndp][1], vb[ndp][3]);
                }
                #pragma unroll
                for (int ndp = 0; ndp < 4; ndp++) {   // Ph*Vl
                    mma_bf16(o[2*ndp],   pah, vl[ndp][0], vl[ndp][2]);
                    mma_bf16(o[2*ndp+1], pah, vl[ndp][1], vl[ndp][3]);
                }
                #pragma unroll
                for (int ndp = 0; ndp < 4; ndp++) {   // Pl*Vh
                    mma_bf16(o[2*ndp],   pal, vb[ndp][0], vb[ndp][2]);
                    mma_bf16(o[2*ndp+1], pal, vb[ndp][1], vb[ndp][3]);
                }
            }
        }
        __syncthreads();
    }

    // ---- finalize ----
    const int bb = bh >> 4;
    const int h  = bh & 15;
    const float i0 = 1.0f / l_[0], i1 = 1.0f / l_[1];
    const int row = q0 + wid * 16 + (lane >> 2);
    #pragma unroll
    for (int nd = 0; nd < 8; nd++) {
        int col = h * 64 + nd * 8 + (lane & 3) * 2;
        float2 v0 = make_float2(o[nd][0] * i0, o[nd][1] * i0);
        float2 v1 = make_float2(o[nd][2] * i1, o[nd][3] * i1);
        *reinterpret_cast<float2*>(g_Att + ((size_t)(bb * Tv) + row)     * Dv + col) = v0;
        *reinterpret_cast<float2*>(g_Att + ((size_t)(bb * Tv) + row + 8) * Dv + col) = v1;
    }
}

// ---------------------------------------------------------------------------
extern "C" void kernel_launch(void* const* d_in, const int* in_sizes, int n_in,
                              void* d_out, int out_size) {
    const float* x    = (const float*)d_in[0];
    const float* Wqkv = (const float*)d_in[1];
    const float* bqkv = (const float*)d_in[2];
    const float* Wout = (const float*)d_in[3];
    const float* bout = (const float*)d_in[4];
    float* out = (float*)d_out;

    void *xh, *xl, *wqh, *wql, *ah, *al, *woh, *wol, *attp;
    cudaGetSymbolAddress(&xh,  g_xh);  cudaGetSymbolAddress(&xl,  g_xl);
    cudaGetSymbolAddress(&wqh, g_wqh); cudaGetSymbolAddress(&wql, g_wql);
    cudaGetSymbolAddress(&ah,  g_ah);  cudaGetSymbolAddress(&al,  g_al);
    cudaGetSymbolAddress(&woh, g_woh); cudaGetSymbolAddress(&wol, g_wol);
    cudaGetSymbolAddress(&attp, g_Att);

    cudaFuncSetAttribute(gemm_mma,  cudaFuncAttributeMaxDynamicSharedMemorySize, 2 * STG_B);
    cudaFuncSetAttribute(flash_mma, cudaFuncAttributeMaxDynamicSharedMemorySize, FLASH_SMEM);

    split_kernel<<<Mv * Kv / 1024, 256>>>(x, (__nv_bfloat16*)xh, (__nv_bfloat16*)xl, Mv * Kv / 4);
    split_kernel<<<QKV_N * Kv / 1024, 256>>>(Wqkv, (__nv_bfloat16*)wqh, (__nv_bfloat16*)wql, QKV_N * Kv / 4);
    split_kernel<<<Dv * Kv / 1024, 256>>>(Wout, (__nv_bfloat16*)woh, (__nv_bfloat16*)wol, Dv * Kv / 4);

    gemm_mma<<<dim3(QKV_N / 128, Mv / 128), 256, 2 * STG_B>>>(
        (__nv_bfloat16*)xh, (__nv_bfloat16*)xl, (__nv_bfloat16*)wqh, (__nv_bfloat16*)wql,
        bqkv, nullptr, 0);

    flash_mma<<<dim3(Tv / 128, Bv * Hv), 256, FLASH_SMEM>>>();

    split_kernel<<<Mv * Dv / 1024, 256>>>((const float*)attp, (__nv_bfloat16*)ah, (__nv_bfloat16*)al, Mv * Dv / 4);
    gemm_mma<<<dim3(Dv / 128, Mv / 128), 256, 2 * STG_B>>>(
        (__nv_bfloat16*)ah, (__nv_bfloat16*)al, (__nv_bfloat16*)woh, (__nv_bfloat16*)wol,
        bout, out, 1);
}

// round 9
// speedup vs baseline: 2.3946x; 1.0023x over previous
#include <cuda_runtime.h>
#include <cuda_bf16.h>
#include <math.h>
#include <stdint.h>

#define Bv 2
#define Tv 2048
#define Dv 1024
#define Hv 16
#define HDv 64
#define Mv 4096          // B*T
#define Kv 1024
#define QKV_N 3072

// ---------------- device scratch (no allocations allowed) ------------------
__device__ __align__(16) __nv_bfloat16 g_Qh[Bv*Hv*Tv*HDv], g_Ql[Bv*Hv*Tv*HDv];
__device__ __align__(16) __nv_bfloat16 g_Kh[Bv*Hv*Tv*HDv], g_Kl[Bv*Hv*Tv*HDv];
__device__ __align__(16) __nv_bfloat16 g_Vh[Bv*Hv*Tv*HDv], g_Vl[Bv*Hv*Tv*HDv];

__device__ __align__(16) __nv_bfloat16 g_xh[Mv*Kv],     g_xl[Mv*Kv];
__device__ __align__(16) __nv_bfloat16 g_wqh[QKV_N*Kv], g_wql[QKV_N*Kv];
__device__ __align__(16) __nv_bfloat16 g_ah[Mv*Kv],     g_al[Mv*Kv];   // attn out hi/lo
__device__ __align__(16) __nv_bfloat16 g_woh[Dv*Kv],    g_wol[Dv*Kv];

// ---------------- PTX helpers ------------------------------------------------
__device__ __forceinline__ uint32_t smem_u32(const void* p) {
    uint32_t a;
    asm("{ .reg .u64 t; cvta.to.shared.u64 t, %1; cvt.u32.u64 %0, t; }" : "=r"(a) : "l"(p));
    return a;
}
__device__ __forceinline__ void cp16(uint32_t s, const void* g) {
    asm volatile("cp.async.cg.shared.global [%0], [%1], 16;" :: "r"(s), "l"(g));
}
#define CP_COMMIT()  asm volatile("cp.async.commit_group;" ::: "memory")
#define CP_WAIT_0()  asm volatile("cp.async.wait_group 0;" ::: "memory")

__device__ __forceinline__ void ldm_x4(uint32_t* r, uint32_t a) {
    asm volatile("ldmatrix.sync.aligned.m8n8.x4.shared.b16 {%0,%1,%2,%3}, [%4];"
        : "=r"(r[0]), "=r"(r[1]), "=r"(r[2]), "=r"(r[3]) : "r"(a));
}
__device__ __forceinline__ void ldm_x4_t(uint32_t* r, uint32_t a) {
    asm volatile("ldmatrix.sync.aligned.m8n8.x4.trans.shared.b16 {%0,%1,%2,%3}, [%4];"
        : "=r"(r[0]), "=r"(r[1]), "=r"(r[2]), "=r"(r[3]) : "r"(a));
}
__device__ __forceinline__ void mma_bf16(float* d, const uint32_t* a,
                                         uint32_t b0, uint32_t b1) {
    asm volatile(
        "mma.sync.aligned.m16n8k16.row.col.f32.bf16.bf16.f32 "
        "{%0,%1,%2,%3}, {%4,%5,%6,%7}, {%8,%9}, {%0,%1,%2,%3};"
        : "+f"(d[0]), "+f"(d[1]), "+f"(d[2]), "+f"(d[3])
        : "r"(a[0]), "r"(a[1]), "r"(a[2]), "r"(a[3]), "r"(b0), "r"(b1));
}
__device__ __forceinline__ void pack_hl(float p0, float p1, uint32_t& h, uint32_t& l) {
    __nv_bfloat16 b0 = __float2bfloat16(p0), b1 = __float2bfloat16(p1);
    h = (uint32_t)__bfloat16_as_ushort(b0) | ((uint32_t)__bfloat16_as_ushort(b1) << 16);
    __nv_bfloat16 r0 = __float2bfloat16(p0 - __bfloat162float(b0));
    __nv_bfloat16 r1 = __float2bfloat16(p1 - __bfloat162float(b1));
    l = (uint32_t)__bfloat16_as_ushort(r0) | ((uint32_t)__bfloat16_as_ushort(r1) << 16);
}

// ---------------- split fp32 -> (hi, lo) bf16 -------------------------------
__global__ __launch_bounds__(256) void split_kernel(const float* __restrict__ s,
                                                    __nv_bfloat16* __restrict__ hi,
                                                    __nv_bfloat16* __restrict__ lo,
                                                    int n4) {
    int i = blockIdx.x * blockDim.x + threadIdx.x;
    if (i >= n4) return;
    float4 v = reinterpret_cast<const float4*>(s)[i];
    ushort4 h, l;
    __nv_bfloat16 b;
    b = __float2bfloat16(v.x); h.x = __bfloat16_as_ushort(b);
    l.x = __bfloat16_as_ushort(__float2bfloat16(v.x - __bfloat162float(b)));
    b = __float2bfloat16(v.y); h.y = __bfloat16_as_ushort(b);
    l.y = __bfloat16_as_ushort(__float2bfloat16(v.y - __bfloat162float(b)));
    b = __float2bfloat16(v.z); h.z = __bfloat16_as_ushort(b);
    l.z = __bfloat16_as_ushort(__float2bfloat16(v.z - __bfloat162float(b)));
    b = __float2bfloat16(v.w); h.w = __bfloat16_as_ushort(b);
    l.w = __bfloat16_as_ushort(__float2bfloat16(v.w - __bfloat162float(b)));
    reinterpret_cast<ushort4*>(hi)[i] = h;
    reinterpret_cast<ushort4*>(lo)[i] = l;
}

// ---------------- HMMA GEMM: single barrier + LDSM/MMA interleave -----------
#define RS     40
#define TILE_B (128 * RS * 2)
#define STG_B  (4 * TILE_B)

#define GEMM_PASS(ACC_A, BB) \
    { \
        _Pragma("unroll") \
        for (int i = 0; i < 4; i++) { \
            _Pragma("unroll") \
            for (int n = 0; n < 4; n++) { \
                const int jp = n >> 1, jo = n & 1; \
                mma_bf16(acc[i][n], ACC_A[i], BB[jp][jo], BB[jp][2 + jo]); \
            } \
        } \
    }

__global__ __launch_bounds__(256, 1) void gemm_mma(const __nv_bfloat16* __restrict__ Ah,
                                                   const __nv_bfloat16* __restrict__ Al,
                                                   const __nv_bfloat16* __restrict__ Bh,
                                                   const __nv_bfloat16* __restrict__ Bl,
                                                   const float* __restrict__ bias,
                                                   float* __restrict__ C, int MODE) {
    extern __shared__ __align__(1024) char dsm[];
    const uint32_t dsb = smem_u32(dsm);

    const int t    = threadIdx.x;
    const int lane = t & 31;
    const int wid  = t >> 5;
    const int wm   = wid & 1;
    const int wn   = wid >> 1;
    const int m0   = blockIdx.y * 128;
    const int n0   = blockIdx.x * 128;

    int      goff[2];
    uint32_t soff[2];
    #pragma unroll
    for (int i = 0; i < 2; i++) {
        int g   = t + i * 256;
        int row = g >> 2;
        int c8  = (g & 3) * 8;
        goff[i] = row * Kv + c8;
        soff[i] = (uint32_t)(row * RS + c8) * 2;
    }
    const __nv_bfloat16* Ahb = Ah + (size_t)m0 * Kv;
    const __nv_bfloat16* Alb = Al + (size_t)m0 * Kv;
    const __nv_bfloat16* Bhb = Bh + (size_t)n0 * Kv;
    const __nv_bfloat16* Blb = Bl + (size_t)n0 * Kv;

    const uint32_t a_base = dsb + (uint32_t)((wm * 64 + (lane & 15)) * RS + (lane >> 4) * 8) * 2;
    const uint32_t b_base = dsb + 2u * TILE_B
                          + (uint32_t)((wn * 32 + (lane & 15)) * RS + (lane >> 4) * 8) * 2;

    float acc[4][4][4];
    #pragma unroll
    for (int i = 0; i < 4; i++)
        #pragma unroll
        for (int n = 0; n < 4; n++)
            #pragma unroll
            for (int r = 0; r < 4; r++) acc[i][n][r] = 0.0f;

    // prologue: chunk 0
    #pragma unroll
    for (int i = 0; i < 2; i++) {
        cp16(dsb + soff[i],              Ahb + goff[i]);
        cp16(dsb + TILE_B + soff[i],     Alb + goff[i]);
        cp16(dsb + 2u*TILE_B + soff[i],  Bhb + goff[i]);
        cp16(dsb + 3u*TILE_B + soff[i],  Blb + goff[i]);
    }
    CP_COMMIT();

    const int NCHUNK = Kv / 32;
    for (int kt = 0; kt < NCHUNK; kt++) {
        const uint32_t s = (uint32_t)(kt & 1) * STG_B;
        CP_WAIT_0();
        __syncthreads();   // single barrier per chunk: reaching here implies all
                           // warps finished last chunk's LDSM reads of buffer s^1
        if (kt + 1 < NCHUNK) {
            const uint32_t s1 = (uint32_t)((kt + 1) & 1) * STG_B;
            const int k1 = (kt + 1) * 32;
            #pragma unroll
            for (int i = 0; i < 2; i++) {
                cp16(dsb + s1 + soff[i],              Ahb + goff[i] + k1);
                cp16(dsb + s1 + TILE_B + soff[i],     Alb + goff[i] + k1);
                cp16(dsb + s1 + 2u*TILE_B + soff[i],  Bhb + goff[i] + k1);
                cp16(dsb + s1 + 3u*TILE_B + soff[i],  Blb + goff[i] + k1);
            }
            CP_COMMIT();
        }

        // ---- ks0 fragments ----
        uint32_t ah0[4][4], al0[4][4], bh0[2][4], bl0[2][4];
        #pragma unroll
        for (int i = 0; i < 4; i++) {
            ldm_x4(ah0[i], a_base + s + (uint32_t)i * (16 * RS * 2));
            ldm_x4(al0[i], a_base + s + TILE_B + (uint32_t)i * (16 * RS * 2));
        }
        #pragma unroll
        for (int j = 0; j < 2; j++) {
            ldm_x4(bh0[j], b_base + s + (uint32_t)j * (16 * RS * 2));
            ldm_x4(bl0[j], b_base + s + TILE_B + (uint32_t)j * (16 * RS * 2));
        }

        GEMM_PASS(ah0, bh0)                      // hh ks0 (16 MMA)

        // load ks1 hi fragments while hh/hl run
        uint32_t ah1[4][4], bh1[2][4];
        #pragma unroll
        for (int i = 0; i < 4; i++)
            ldm_x4(ah1[i], a_base + s + 32 + (uint32_t)i * (16 * RS * 2));
        #pragma unroll
        for (int j = 0; j < 2; j++)
            ldm_x4(bh1[j], b_base + s + 32 + (uint32_t)j * (16 * RS * 2));

        GEMM_PASS(ah0, bl0)                      // hl ks0

        // load ks1 lo fragments
        uint32_t al1[4][4], bl1[2][4];
        #pragma unroll
        for (int i = 0; i < 4; i++)
            ldm_x4(al1[i], a_base + s + TILE_B + 32 + (uint32_t)i * (16 * RS * 2));
        #pragma unroll
        for (int j = 0; j < 2; j++)
            ldm_x4(bl1[j], b_base + s + TILE_B + 32 + (uint32_t)j * (16 * RS * 2));

        GEMM_PASS(al0, bh0)                      // lh ks0
        GEMM_PASS(ah1, bh1)                      // hh ks1
        GEMM_PASS(ah1, bl1)                      // hl ks1
        GEMM_PASS(al1, bh1)                      // lh ks1
    }

    if (MODE == 0) {
        #pragma unroll
        for (int i = 0; i < 4; i++)
            #pragma unroll
            for (int n = 0; n < 4; n++)
                #pragma unroll
                for (int r = 0; r < 4; r++) {
                    int row = m0 + wm * 64 + i * 16 + (lane >> 2) + (r >> 1) * 8;
                    int col = n0 + wn * 32 + n * 8 + (lane & 3) * 2 + (r & 1);
                    float v = acc[i][n][r] + __ldg(bias + col);
                    int bb = row >> 11;
                    int tt = row & (Tv - 1);
                    int h  = col / 192;
                    int rr = col - h * 192;
                    size_t off = (((size_t)(bb * Hv + h)) * Tv + tt) * HDv + (rr & 63);
                    __nv_bfloat16 hi = __float2bfloat16(v);
                    __nv_bfloat16 lo = __float2bfloat16(v - __bfloat162float(hi));
                    if (rr < 64)       { g_Qh[off] = hi; g_Ql[off] = lo; }
                    else if (rr < 128) { g_Kh[off] = hi; g_Kl[off] = lo; }
                    else               { g_Vh[off] = hi; g_Vl[off] = lo; }
                }
    } else {
        #pragma unroll
        for (int i = 0; i < 4; i++)
            #pragma unroll
            for (int n = 0; n < 4; n++) {
                int row = m0 + wm * 64 + i * 16 + (lane >> 2);
                int col = n0 + wn * 32 + n * 8 + (lane & 3) * 2;
                float b0 = __ldg(bias + col), b1 = __ldg(bias + col + 1);
                float2 v0 = make_float2(acc[i][n][0] + b0, acc[i][n][1] + b1);
                float2 v1 = make_float2(acc[i][n][2] + b0, acc[i][n][3] + b1);
                *reinterpret_cast<float2*>(C + (size_t)row * Dv + col)       = v0;
                *reinterpret_cast<float2*>(C + (size_t)(row + 8) * Dv + col) = v1;
            }
    }
}

// ---------------- flash attention, HMMA split-precision ---------------------
#define FRS        72
#define FQ_TILE_B  (128 * FRS * 2)
#define FK_TILE_B  (64 * FRS * 2)
#define FST_B      (4 * FK_TILE_B)
#define FLASH_SMEM (2 * FQ_TILE_B + 2 * FST_B)

__global__ __launch_bounds__(256, 1) void flash_mma() {
    extern __shared__ __align__(1024) char fsm[];
    const uint32_t base = smem_u32(fsm);

    const int t    = threadIdx.x;
    const int lane = t & 31;
    const int wid  = t >> 5;
    const int bh   = blockIdx.y;
    const int qt   = blockIdx.x;
    const int q0   = qt * 128;
    const int NKT  = 2 * qt + 2;

    const __nv_bfloat16* Qhg = g_Qh + ((size_t)bh * Tv + q0) * HDv;
    const __nv_bfloat16* Qlg = g_Ql + ((size_t)bh * Tv + q0) * HDv;
    const __nv_bfloat16* Khg = g_Kh + (size_t)bh * Tv * HDv;
    const __nv_bfloat16* Klg = g_Kl + (size_t)bh * Tv * HDv;
    const __nv_bfloat16* Vhg = g_Vh + (size_t)bh * Tv * HDv;
    const __nv_bfloat16* Vlg = g_Vl + (size_t)bh * Tv * HDv;

    #pragma unroll
    for (int i = 0; i < 4; i++) {
        int g = t + i * 256;
        int r = g >> 3;
        int c8 = (g & 7) * 8;
        uint32_t so = (uint32_t)(r * FRS + c8) * 2;
        cp16(base + so,             Qhg + r * HDv + c8);
        cp16(base + FQ_TILE_B + so, Qlg + r * HDv + c8);
    }
    CP_COMMIT();
    {
        int g = t, r = g >> 3, c8 = (g & 7) * 8;
        int g2 = t + 256, r2 = g2 >> 3, c82 = (g2 & 7) * 8;
        uint32_t st = base + 2 * FQ_TILE_B;
        uint32_t so  = (uint32_t)(r  * FRS + c8)  * 2;
        uint32_t so2 = (uint32_t)(r2 * FRS + c82) * 2;
        int go  = r  * HDv + c8;
        int go2 = r2 * HDv + c82;
        cp16(st + so,                 Khg + go);  cp16(st + so2,                 Khg + go2);
        cp16(st + FK_TILE_B + so,     Klg + go);  cp16(st + FK_TILE_B + so2,     Klg + go2);
        cp16(st + 2*FK_TILE_B + so,   Vhg + go);  cp16(st + 2*FK_TILE_B + so2,   Vhg + go2);
        cp16(st + 3*FK_TILE_B + so,   Vlg + go);  cp16(st + 3*FK_TILE_B + so2,   Vlg + go2);
    }
    CP_COMMIT();

    const int qw0 = q0 + wid * 16;
    float m_[2] = {-INFINITY, -INFINITY};
    float l_[2] = {0.0f, 0.0f};
    float o[8][4];
    #pragma unroll
    for (int n = 0; n < 8; n++)
        #pragma unroll
        for (int e = 0; e < 4; e++) o[n][e] = 0.0f;

    uint32_t qh[4][4], ql[4][4];

    const uint32_t q_lmb = base + (uint32_t)((wid * 16 + (lane & 15)) * FRS + (lane >> 4) * 8) * 2;
    const uint32_t k_lane = (uint32_t)((lane & 15) * FRS + (lane >> 4) * 8) * 2;
    const uint32_t v_lane = (uint32_t)(((lane & 7) + ((lane >> 4) << 3)) * FRS + ((lane >> 3) & 1) * 8) * 2;

    for (int kt = 0; kt < NKT; kt++) {
        const uint32_t st = base + 2 * FQ_TILE_B + (uint32_t)(kt & 1) * FST_B;
        CP_WAIT_0();
        __syncthreads();   // single barrier per tile (see gemm_mma comment)
        if (kt + 1 < NKT) {
            const uint32_t st1 = base + 2 * FQ_TILE_B + (uint32_t)((kt + 1) & 1) * FST_B;
            const int kr = (kt + 1) * 64;
            int g = t, r = g >> 3, c8 = (g & 7) * 8;
            int g2 = t + 256, r2 = g2 >> 3, c82 = (g2 & 7) * 8;
            uint32_t so  = (uint32_t)(r  * FRS + c8)  * 2;
            uint32_t so2 = (uint32_t)(r2 * FRS + c82) * 2;
            int go  = (kr + r)  * HDv + c8;
            int go2 = (kr + r2) * HDv + c82;
            cp16(st1 + so,               Khg + go);  cp16(st1 + so2,               Khg + go2);
            cp16(st1 + FK_TILE_B + so,   Klg + go);  cp16(st1 + FK_TILE_B + so2,   Klg + go2);
            cp16(st1 + 2*FK_TILE_B + so, Vhg + go);  cp16(st1 + 2*FK_TILE_B + so2, Vhg + go2);
            cp16(st1 + 3*FK_TILE_B + so, Vlg + go);  cp16(st1 + 3*FK_TILE_B + so2, Vlg + go2);
            CP_COMMIT();
        }

        if (kt == 0) {
            #pragma unroll
            for (int kg = 0; kg < 4; kg++) {
                ldm_x4(qh[kg], q_lmb + kg * 32);
                ldm_x4(ql[kg], q_lmb + FQ_TILE_B + kg * 32);
            }
        }

        const int k0 = kt * 64;
        if (k0 <= qw0 + 15) {
            // ---- S = Q K^T (split, pass-major) ----
            float sa[8][4];
            #pragma unroll
            for (int n = 0; n < 8; n++)
                #pragma unroll
                for (int e = 0; e < 4; e++) sa[n][e] = 0.0f;

            #pragma unroll
            for (int kg = 0; kg < 4; kg++) {
                uint32_t kb[4][4], kl[4][4];
                #pragma unroll
                for (int np = 0; np < 4; np++) {
                    uint32_t addr = st + k_lane + (uint32_t)(np * 16 * FRS * 2) + kg * 32;
                    ldm_x4(kb[np], addr);
                    ldm_x4(kl[np], addr + FK_TILE_B);
                }
                #pragma unroll
                for (int np = 0; np < 4; np++) {
                    mma_bf16(sa[2*np],   qh[kg], kb[np][0], kb[np][2]);
                    mma_bf16(sa[2*np+1], qh[kg], kb[np][1], kb[np][3]);
                }
                #pragma unroll
                for (int np = 0; np < 4; np++) {
                    mma_bf16(sa[2*np],   qh[kg], kl[np][0], kl[np][2]);
                    mma_bf16(sa[2*np+1], qh[kg], kl[np][1], kl[np][3]);
                }
                #pragma unroll
                for (int np = 0; np < 4; np++) {
                    mma_bf16(sa[2*np],   ql[kg], kb[np][0], kb[np][2]);
                    mma_bf16(sa[2*np+1], ql[kg], kb[np][1], kb[np][3]);
                }
            }

            // ---- scale + causal mask ----
            const int r0 = qw0 + (lane >> 2);
            #pragma unroll
            for (int n = 0; n < 8; n++)
                #pragma unroll
                for (int e = 0; e < 4; e++) {
                    float v = sa[n][e] * 0.125f;
                    int rr = r0 + (e >> 1) * 8;
                    int cc = k0 + n * 8 + (lane & 3) * 2 + (e & 1);
                    sa[n][e] = (cc > rr) ? -INFINITY : v;
                }

            // ---- online softmax ----
            float corr[2];
            #pragma unroll
            for (int rh = 0; rh < 2; rh++) {
                float mx = -INFINITY;
                #pragma unroll
                for (int n = 0; n < 8; n++)
                    mx = fmaxf(mx, fmaxf(sa[n][2*rh], sa[n][2*rh+1]));
                mx = fmaxf(mx, __shfl_xor_sync(0xffffffffu, mx, 1));
                mx = fmaxf(mx, __shfl_xor_sync(0xffffffffu, mx, 2));
                float mnew = fmaxf(m_[rh], mx);
                corr[rh] = __expf(m_[rh] - mnew);
                m_[rh] = mnew;
                float rs = 0.0f;
                #pragma unroll
                for (int n = 0; n < 8; n++) {
                    float p0 = __expf(sa[n][2*rh]   - mnew);
                    float p1 = __expf(sa[n][2*rh+1] - mnew);
                    sa[n][2*rh] = p0; sa[n][2*rh+1] = p1;
                    rs += p0 + p1;
                }
                rs += __shfl_xor_sync(0xffffffffu, rs, 1);
                rs += __shfl_xor_sync(0xffffffffu, rs, 2);
                l_[rh] = l_[rh] * corr[rh] + rs;
            }
            #pragma unroll
            for (int n = 0; n < 8; n++) {
                o[n][0] *= corr[0]; o[n][1] *= corr[0];
                o[n][2] *= corr[1]; o[n][3] *= corr[1];
            }

            // ---- O += P V (split, pass-major) ----
            #pragma unroll
            for (int kg = 0; kg < 4; kg++) {
                uint32_t pah[4], pal[4];
                pack_hl(sa[2*kg][0],   sa[2*kg][1],   pah[0], pal[0]);
                pack_hl(sa[2*kg][2],   sa[2*kg][3],   pah[1], pal[1]);
                pack_hl(sa[2*kg+1][0], sa[2*kg+1][1], pah[2], pal[2]);
                pack_hl(sa[2*kg+1][2], sa[2*kg+1][3], pah[3], pal[3]);
                uint32_t vb[4][4], vl[4][4];
                #pragma unroll
                for (int ndp = 0; ndp < 4; ndp++) {
                    uint32_t addr = st + 2*FK_TILE_B + v_lane
                                  + (uint32_t)(kg * 16 * FRS * 2) + ndp * 32;
                    ldm_x4_t(vb[ndp], addr);
                    ldm_x4_t(vl[ndp], addr + FK_TILE_B);
                }
                #pragma unroll
                for (int ndp = 0; ndp < 4; ndp++) {
                    mma_bf16(o[2*ndp],   pah, vb[ndp][0], vb[ndp][2]);
                    mma_bf16(o[2*ndp+1], pah, vb[ndp][1], vb[ndp][3]);
                }
                #pragma unroll
                for (int ndp = 0; ndp < 4; ndp++) {
                    mma_bf16(o[2*ndp],   pah, vl[ndp][0], vl[ndp][2]);
                    mma_bf16(o[2*ndp+1], pah, vl[ndp][1], vl[ndp][3]);
                }
                #pragma unroll
                for (int ndp = 0; ndp < 4; ndp++) {
                    mma_bf16(o[2*ndp],   pal, vb[ndp][0], vb[ndp][2]);
                    mma_bf16(o[2*ndp+1], pal, vb[ndp][1], vb[ndp][3]);
                }
            }
        }
    }

    // ---- finalize: write bf16 hi/lo attention output directly --------------
    const int bb = bh >> 4;
    const int h  = bh & 15;
    const float i0 = 1.0f / l_[0], i1 = 1.0f / l_[1];
    const int row = q0 + wid * 16 + (lane >> 2);
    const size_t base0 = ((size_t)(bb * Tv) + row) * Dv;
    const size_t base1 = base0 + (size_t)8 * Dv;
    #pragma unroll
    for (int nd = 0; nd < 8; nd++) {
        int col = h * 64 + nd * 8 + (lane & 3) * 2;
        uint32_t h0, l0, h1, l1;
        pack_hl(o[nd][0] * i0, o[nd][1] * i0, h0, l0);
        pack_hl(o[nd][2] * i1, o[nd][3] * i1, h1, l1);
        *reinterpret_cast<uint32_t*>(&g_ah[base0 + col]) = h0;
        *reinterpret_cast<uint32_t*>(&g_al[base0 + col]) = l0;
        *reinterpret_cast<uint32_t*>(&g_ah[base1 + col]) = h1;
        *reinterpret_cast<uint32_t*>(&g_al[base1 + col]) = l1;
    }
}

// ---------------------------------------------------------------------------
extern "C" void kernel_launch(void* const* d_in, const int* in_sizes, int n_in,
                              void* d_out, int out_size) {
    const float* x    = (const float*)d_in[0];
    const float* Wqkv = (const float*)d_in[1];
    const float* bqkv = (const float*)d_in[2];
    const float* Wout = (const float*)d_in[3];
    const float* bout = (const float*)d_in[4];
    float* out = (float*)d_out;

    void *xh, *xl, *wqh, *wql, *ah, *al, *woh, *wol;
    cudaGetSymbolAddress(&xh,  g_xh);  cudaGetSymbolAddress(&xl,  g_xl);
    cudaGetSymbolAddress(&wqh, g_wqh); cudaGetSymbolAddress(&wql, g_wql);
    cudaGetSymbolAddress(&ah,  g_ah);  cudaGetSymbolAddress(&al,  g_al);
    cudaGetSymbolAddress(&woh, g_woh); cudaGetSymbolAddress(&wol, g_wol);

    cudaFuncSetAttribute(gemm_mma,  cudaFuncAttributeMaxDynamicSharedMemorySize, 2 * STG_B);
    cudaFuncSetAttribute(flash_mma, cudaFuncAttributeMaxDynamicSharedMemorySize, FLASH_SMEM);

    split_kernel<<<Mv * Kv / 1024, 256>>>(x, (__nv_bfloat16*)xh, (__nv_bfloat16*)xl, Mv * Kv / 4);
    split_kernel<<<QKV_N * Kv / 1024, 256>>>(Wqkv, (__nv_bfloat16*)wqh, (__nv_bfloat16*)wql, QKV_N * Kv / 4);
    split_kernel<<<Dv * Kv / 1024, 256>>>(Wout, (__nv_bfloat16*)woh, (__nv_bfloat16*)wol, Dv * Kv / 4);

    // 1) QKV projection -> bf16 hi/lo Q,K,V
    gemm_mma<<<dim3(QKV_N / 128, Mv / 128), 256, 2 * STG_B>>>(
        (__nv_bfloat16*)xh, (__nv_bfloat16*)xl, (__nv_bfloat16*)wqh, (__nv_bfloat16*)wql,
        bqkv, nullptr, 0);

    // 2) causal flash attention -> bf16 hi/lo attention output (split fused)
    flash_mma<<<dim3(Tv / 128, Bv * Hv), 256, FLASH_SMEM>>>();

    // 3) output projection
    gemm_mma<<<dim3(Dv / 128, Mv / 128), 256, 2 * STG_B>>>(
        (__nv_bfloat16*)ah, (__nv_bfloat16*)al, (__nv_bfloat16*)woh, (__nv_bfloat16*)wol,
        bout, out, 1);
}